// round 3
// baseline (speedup 1.0000x reference)
#include <cuda_runtime.h>
#include <cstdint>

#define B_   8
#define N_   1024
#define NIN_ 64
#define H_   128
#define F_   192
#define TI_A 32
#define TI_B 64
#define WPITCH 194   // 192 + 2 pad, keeps f32x2 loads 8B-aligned, conflict-light

typedef unsigned long long u64;

// ---------- f32x2 packed-FMA helpers (FFMA2 only reachable via PTX) ----------
__device__ __forceinline__ u64 pack2(float x, float y) {
    u64 r; asm("mov.b64 %0, {%1, %2};" : "=l"(r) : "f"(x), "f"(y)); return r;
}
__device__ __forceinline__ float2 unpack2(u64 v) {
    float2 r; asm("mov.b64 {%0, %1}, %2;" : "=f"(r.x), "=f"(r.y) : "l"(v)); return r;
}
__device__ __forceinline__ void ffma2(u64& d, u64 a, u64 b) {
    asm("fma.rn.f32x2 %0, %1, %2, %0;" : "+l"(d) : "l"(a), "l"(b));
}

// ---------- scratch (device globals: no allocations allowed) ----------
__device__ float  g_hl[B_ * N_ * H_];          // 4 MB
__device__ float  g_hr[B_ * N_ * H_];          // 4 MB
__device__ float2 g_tp[B_ * N_ * H_];          // 8 MB: (k0,k1) packed per g

// =====================================================================
// Kernel A: hl[b,i,h] = relu(b_l[h] + Wl[:,0:64]·x[i] + Wl[:,64:128]·x[i-1] + Wl[:,128:192]·x[i+1])
//           hr[b,i,h] = relu(b_r[h] + Wr[:,0:64]·x[i] + Wr[:,64:128]·x[i+1] + Wr[:,128:192]·x[i-1])
// One block = 32 rows of one batch; 256 threads = 128 hl-units + 128 hr-units.
// f32x2 pairs along the f (reduction) axis; horizontal add at the end.
// =====================================================================
__global__ __launch_bounds__(256, 1)
void hidden_kernel(const float* __restrict__ x,
                   const float* __restrict__ Wl, const float* __restrict__ bl,
                   const float* __restrict__ Wr, const float* __restrict__ br)
{
    extern __shared__ float sm[];
    float* sx = sm;                        // [TI_A+2][64]
    float* sW = sm + (TI_A + 2) * NIN_;    // [256][WPITCH]: rows 0..127 = Wl, 128..255 = Wr

    const int b   = blockIdx.y;
    const int i0  = blockIdx.x * TI_A;
    const int tid = threadIdx.x;
    const float* xb = x + (size_t)b * N_ * NIN_;

    // x rows i0-1 .. i0+TI_A (zero-padded at batch edges)
    for (int idx = tid; idx < (TI_A + 2) * NIN_; idx += 256) {
        int r = idx >> 6, c = idx & 63;
        int gi = i0 - 1 + r;
        sx[idx] = (gi >= 0 && gi < N_) ? xb[gi * NIN_ + c] : 0.f;
    }
    // W (row-major [h][f]) -> smem, coalesced reads, conflict-free writes
    for (int idx = tid; idx < H_ * F_; idx += 256) {
        int f = idx % F_, h = idx / F_;
        sW[h * WPITCH + f]          = Wl[idx];
        sW[(h + 128) * WPITCH + f]  = Wr[idx];
    }
    __syncthreads();

    const int hh   = tid;
    const int side = hh >> 7;   // 0 = left, 1 = right
    const int h    = hh & 127;

    u64 acc[TI_A];
    #pragma unroll
    for (int m = 0; m < TI_A; m++) acc[m] = 0ull;

    const float* wrow = sW + hh * WPITCH;
    #pragma unroll 4
    for (int fp = 0; fp < F_ / 2; fp++) {
        const int f   = 2 * fp;
        const int seg = f >> 6;
        const int fc  = f & 63;
        // local sx row offset for this segment: xl = [x_i, x_{i-1}, x_{i+1}], xr = [x_i, x_{i+1}, x_{i-1}]
        const int off = (side == 0) ? ((seg == 0) ? 1 : (seg == 1) ? 0 : 2)
                                    : ((seg == 0) ? 1 : (seg == 1) ? 2 : 0);
        const u64 w2 = *(const u64*)(wrow + f);
        const float* xs = sx + off * NIN_ + fc;
        #pragma unroll
        for (int m = 0; m < TI_A; m++) {
            u64 x2 = *(const u64*)(xs + m * NIN_);   // warp-broadcast
            ffma2(acc[m], w2, x2);
        }
    }

    const float bias = (side == 0) ? bl[h] : br[h];
    float* outp = (side == 0 ? g_hl : g_hr) + ((size_t)b * N_ + i0) * H_ + h;
    #pragma unroll
    for (int m = 0; m < TI_A; m++) {
        float2 p = unpack2(acc[m]);
        outp[m * H_] = fmaxf(p.x + p.y + bias, 0.f);
    }
}

// =====================================================================
// Kernel B: t[b,i,k,g] = sum_h hl[b,i,h] * W_bil[k,h,g], stored packed over k:
//           g_tp[(b*N+i)*128 + g] = (t_k0, t_k1)   -> f32x2 pairs along k
// One block = 64 rows; W_bil pre-paired in smem as float2[h][g].
// =====================================================================
__global__ __launch_bounds__(256, 1)
void tform_kernel(const float* __restrict__ Wbil)
{
    extern __shared__ float sm[];
    float2* sWb = (float2*)sm;             // [128][128] float2 (k-pairs) = 128 KB
    float*  shl = sm + 2 * H_ * H_;        // [64][128] = 32 KB

    const int b   = blockIdx.y;
    const int i0  = blockIdx.x * TI_B;
    const int tid = threadIdx.x;

    for (int idx = tid; idx < H_ * H_; idx += 256)
        sWb[idx] = make_float2(Wbil[idx], Wbil[H_ * H_ + idx]);

    const float* hlp = g_hl + ((size_t)b * N_ + i0) * H_;
    for (int idx = tid; idx < TI_B * H_; idx += 256) shl[idx] = hlp[idx];
    __syncthreads();

    const int g  = tid & 127;
    const int rg = tid >> 7;               // 0 / 1 : which 32-row half

    u64 acc[32];
    #pragma unroll
    for (int m = 0; m < 32; m++) acc[m] = 0ull;

    const float* xrow = shl + (rg * 32) * H_;
    #pragma unroll 2
    for (int h = 0; h < H_; h++) {
        const u64 w2 = *(const u64*)(sWb + h * H_ + g);
        #pragma unroll
        for (int m = 0; m < 32; m++) {
            float xv = xrow[m * H_ + h];   // warp-broadcast
            ffma2(acc[m], w2, pack2(xv, xv));
        }
    }

    float2* outp = g_tp + ((size_t)b * N_ + i0 + rg * 32) * H_ + g;
    #pragma unroll
    for (int m = 0; m < 32; m++) outp[m * H_] = unpack2(acc[m]);
}

// =====================================================================
// Kernel C (dominant): out[b,i,j,(k0,k1)] = b_bil + sum_g tp[b,i,g] * hr[b,j,g]
// 64x64 (i,j) tile per block, 4i x 4j x (2k packed) register tile per thread.
// Warp arranged 4(li) x 8(lj) so smem reads are mostly broadcast -> FFMA2-bound.
// =====================================================================
__global__ __launch_bounds__(256, 1)
void pair_kernel(const float* __restrict__ bbil, float2* __restrict__ out)
{
    extern __shared__ float sm[];
    float2* stp = (float2*)sm;             // [64][128] float2 = 64 KB
    float*  shr = sm + 2 * 64 * H_;        // [64][128] = 32 KB

    const int b   = blockIdx.z;
    const int i0  = blockIdx.y * 64;
    const int j0  = blockIdx.x * 64;
    const int tid = threadIdx.x;

    // tile loads, float4-vectorized
    const float4* src_t = (const float4*)(g_tp + ((size_t)b * N_ + i0) * H_);
    float4* dst_t = (float4*)stp;
    for (int idx = tid; idx < 64 * H_ / 2; idx += 256) dst_t[idx] = src_t[idx];
    const float4* src_r = (const float4*)(g_hr + ((size_t)b * N_ + j0) * H_);
    float4* dst_r = (float4*)shr;
    for (int idx = tid; idx < 64 * H_ / 4; idx += 256) dst_r[idx] = src_r[idx];
    __syncthreads();

    const int warp = tid >> 5, lane = tid & 31;
    const int li = lane >> 3, lj = lane & 7;      // 4 x 8 in-warp grid
    const int wy = warp >> 1, wx = warp & 1;      // 4 x 2 warp grid
    const int iq = wy * 4 + li;                   // 0..15 (i quads)
    const int jq = wx * 8 + lj;                   // 0..15 (j quads)

    const u64 bias = pack2(bbil[0], bbil[1]);
    u64 acc[4][4];
    #pragma unroll
    for (int u = 0; u < 4; u++)
        #pragma unroll
        for (int v = 0; v < 4; v++) acc[u][v] = bias;

    const float2* arow = stp + iq * 4 * H_;
    const float*  brow = shr + jq * 4 * H_;

    #pragma unroll 4
    for (int g = 0; g < H_; g++) {
        u64 a2[4], bp[4];
        #pragma unroll
        for (int u = 0; u < 4; u++) a2[u] = *(const u64*)(arow + u * H_ + g);
        #pragma unroll
        for (int v = 0; v < 4; v++) { float bv = brow[v * H_ + g]; bp[v] = pack2(bv, bv); }
        #pragma unroll
        for (int u = 0; u < 4; u++)
            #pragma unroll
            for (int v = 0; v < 4; v++)
                ffma2(acc[u][v], a2[u], bp[v]);
    }

    #pragma unroll
    for (int u = 0; u < 4; u++) {
        const int i = i0 + iq * 4 + u;
        float4* o4 = (float4*)(out + ((size_t)b * N_ + i) * N_ + j0 + jq * 4);
        float2 r0 = unpack2(acc[u][0]), r1 = unpack2(acc[u][1]);
        float2 r2 = unpack2(acc[u][2]), r3 = unpack2(acc[u][3]);
        o4[0] = make_float4(r0.x, r0.y, r1.x, r1.y);
        o4[1] = make_float4(r2.x, r2.y, r3.x, r3.y);
    }
}

// =====================================================================
extern "C" void kernel_launch(void* const* d_in, const int* in_sizes, int n_in,
                              void* d_out, int out_size)
{
    (void)in_sizes; (void)n_in; (void)out_size;
    const float* x  = (const float*)d_in[0];
    const float* Wl = (const float*)d_in[1];
    const float* bl = (const float*)d_in[2];
    const float* Wr = (const float*)d_in[3];
    const float* br = (const float*)d_in[4];
    const float* Wb = (const float*)d_in[5];
    const float* bb = (const float*)d_in[6];

    const int smemA = ((TI_A + 2) * NIN_ + 256 * WPITCH) * 4;   // 207,360 B
    const int smemB = (2 * H_ * H_ + TI_B * H_) * 4;            // 163,840 B
    const int smemC = (2 * 64 * H_ + 64 * H_) * 4;              //  98,304 B
    cudaFuncSetAttribute(hidden_kernel, cudaFuncAttributeMaxDynamicSharedMemorySize, smemA);
    cudaFuncSetAttribute(tform_kernel,  cudaFuncAttributeMaxDynamicSharedMemorySize, smemB);
    cudaFuncSetAttribute(pair_kernel,   cudaFuncAttributeMaxDynamicSharedMemorySize, smemC);

    hidden_kernel<<<dim3(N_ / TI_A, B_), 256, smemA>>>(x, Wl, bl, Wr, br);
    tform_kernel <<<dim3(N_ / TI_B, B_), 256, smemB>>>(Wb);
    pair_kernel  <<<dim3(16, 16, B_),    256, smemC>>>(bb, (float2*)d_out);
}

// round 7
// speedup vs baseline: 3.0820x; 3.0820x over previous
#include <cuda_runtime.h>
#include <cuda_bf16.h>
#include <cstdint>

#define B_   8
#define N_   1024
#define NIN_ 64
#define H_   128
#define F_   192
#define WPITCH 194

typedef unsigned long long u64;

// ---------------- f32x2 packed-FMA helpers ----------------
__device__ __forceinline__ u64 pack2(float x, float y) {
    u64 r; asm("mov.b64 %0, {%1, %2};" : "=l"(r) : "f"(x), "f"(y)); return r;
}
__device__ __forceinline__ float2 unpack2(u64 v) {
    float2 r; asm("mov.b64 {%0, %1}, %2;" : "=f"(r.x), "=f"(r.y) : "l"(v)); return r;
}
__device__ __forceinline__ void ffma2(u64& d, u64 a, u64 b) {
    asm("fma.rn.f32x2 %0, %1, %2, %0;" : "+l"(d) : "l"(a), "l"(b));
}

// ---------------- scratch (device globals) ----------------
__device__ float g_hl[B_ * N_ * H_];                               // 4 MB fp32
__device__ __align__(16) __nv_bfloat16 g_hr_hi[B_ * N_ * H_];      // 2 MB
__device__ __align__(16) __nv_bfloat16 g_hr_lo[B_ * N_ * H_];
__device__ __align__(16) __nv_bfloat16 g_t_hi[2 * B_ * N_ * H_];   // 4 MB (k planes)
__device__ __align__(16) __nv_bfloat16 g_t_lo[2 * B_ * N_ * H_];

__device__ __forceinline__ uint32_t smem_u32(const void* p) {
    uint32_t a;
    asm("{ .reg .u64 t; cvta.to.shared.u64 t, %1; cvt.u32.u64 %0, t; }" : "=r"(a) : "l"(p));
    return a;
}
// ---------------- tensor-core primitives (no 'a'-suffix PTX) ----------------
__device__ __forceinline__ void ldsm4(uint32_t& a0, uint32_t& a1, uint32_t& a2, uint32_t& a3, uint32_t addr) {
    asm volatile("ldmatrix.sync.aligned.m8n8.x4.shared.b16 {%0,%1,%2,%3}, [%4];"
        : "=r"(a0), "=r"(a1), "=r"(a2), "=r"(a3) : "r"(addr));
}
__device__ __forceinline__ void ldsm2(uint32_t& b0, uint32_t& b1, uint32_t addr) {
    asm volatile("ldmatrix.sync.aligned.m8n8.x2.shared.b16 {%0,%1}, [%2];"
        : "=r"(b0), "=r"(b1) : "r"(addr));
}
__device__ __forceinline__ void mma_bf16(float* c, const uint32_t* a, const uint32_t* b) {
    asm volatile("mma.sync.aligned.m16n8k16.row.col.f32.bf16.bf16.f32 "
        "{%0,%1,%2,%3}, {%4,%5,%6,%7}, {%8,%9}, {%0,%1,%2,%3};"
        : "+f"(c[0]), "+f"(c[1]), "+f"(c[2]), "+f"(c[3])
        : "r"(a[0]), "r"(a[1]), "r"(a[2]), "r"(a[3]), "r"(b[0]), "r"(b[1]));
}

// =====================================================================
// Kernel A: one side per block (smem 108 KB -> 2 CTAs/SM).
//   side 0: g_hl fp32;  side 1: hr hi/lo bf16 split.
// =====================================================================
__global__ __launch_bounds__(256, 2)
void hidden_kernel(const float* __restrict__ x,
                   const float* __restrict__ Wl, const float* __restrict__ bl,
                   const float* __restrict__ Wr, const float* __restrict__ br)
{
    extern __shared__ float sm[];
    float* sx = sm;                      // [34][64]
    float* sW = sm + 34 * NIN_;          // [128][WPITCH]

    const int b    = blockIdx.y;
    const int i0   = blockIdx.x * 32;
    const int side = blockIdx.z;
    const int tid  = threadIdx.x;
    const float* xb = x + (size_t)b * N_ * NIN_;
    const float* W  = side ? Wr : Wl;

    for (int idx = tid; idx < 34 * NIN_; idx += 256) {
        int r = idx >> 6, c = idx & 63;
        int gi = i0 - 1 + r;
        sx[idx] = (gi >= 0 && gi < N_) ? xb[gi * NIN_ + c] : 0.f;
    }
    for (int idx = tid; idx < H_ * F_; idx += 256) {
        int f = idx % F_, h = idx / F_;
        sW[h * WPITCH + f] = W[idx];
    }
    __syncthreads();

    const int h  = tid & 127;
    const int rg = tid >> 7;             // rows rg*16 .. rg*16+15

    u64 acc[16];
    #pragma unroll
    for (int m = 0; m < 16; m++) acc[m] = 0ull;

    const float* wrow = sW + h * WPITCH;
    #pragma unroll 4
    for (int fp = 0; fp < F_ / 2; fp++) {
        const int f   = 2 * fp;
        const int seg = f >> 6;
        const int fc  = f & 63;
        // xl = [x_i, x_{i-1}, x_{i+1}], xr = [x_i, x_{i+1}, x_{i-1}]; sx row r <-> global i0-1+r
        const int off = (side == 0) ? ((seg == 0) ? 1 : (seg == 1) ? 0 : 2)
                                    : ((seg == 0) ? 1 : (seg == 1) ? 2 : 0);
        const u64 w2 = *(const u64*)(wrow + f);
        const float* xs = sx + (off + rg * 16) * NIN_ + fc;
        #pragma unroll
        for (int m = 0; m < 16; m++) {
            u64 x2 = *(const u64*)(xs + m * NIN_);   // warp-broadcast
            ffma2(acc[m], w2, x2);
        }
    }

    const float bias = side ? br[h] : bl[h];
    const size_t base = ((size_t)b * N_ + i0 + rg * 16) * H_ + h;
    if (side == 0) {
        #pragma unroll
        for (int m = 0; m < 16; m++) {
            float2 p = unpack2(acc[m]);
            g_hl[base + m * H_] = fmaxf(p.x + p.y + bias, 0.f);
        }
    } else {
        #pragma unroll
        for (int m = 0; m < 16; m++) {
            float2 p = unpack2(acc[m]);
            float v = fmaxf(p.x + p.y + bias, 0.f);
            __nv_bfloat16 hi = __float2bfloat16_rn(v);
            __nv_bfloat16 lo = __float2bfloat16_rn(v - __bfloat162float(hi));
            g_hr_hi[base + m * H_] = hi;
            g_hr_lo[base + m * H_] = lo;
        }
    }
}

// =====================================================================
// Kernel B: one k-channel per block; f32x2 packs (g, g+64).
//   smem 80 KB -> 2 CTAs/SM. Emits bf16 hi/lo planes of t directly.
// =====================================================================
__global__ __launch_bounds__(256, 2)
void tform_kernel(const float* __restrict__ Wbil)
{
    extern __shared__ float sm[];
    float2* sWb = (float2*)sm;           // [128][64]: (W[k][h][g], W[k][h][g+64])
    float*  shl = sm + 2 * H_ * 64;      // [32][128]

    const int b   = blockIdx.y;
    const int i0  = blockIdx.x * 32;
    const int k   = blockIdx.z;
    const int tid = threadIdx.x;
    const float* Wk = Wbil + (size_t)k * H_ * H_;

    for (int idx = tid; idx < H_ * 64; idx += 256) {
        int h = idx >> 6, gp = idx & 63;
        sWb[idx] = make_float2(Wk[h * H_ + gp], Wk[h * H_ + gp + 64]);
    }
    const float* hlp = g_hl + ((size_t)b * N_ + i0) * H_;
    for (int idx = tid; idx < 32 * H_; idx += 256) shl[idx] = hlp[idx];
    __syncthreads();

    const int gp = tid & 63;
    const int rg = tid >> 6;             // rows rg*8 .. rg*8+7

    u64 acc[8];
    #pragma unroll
    for (int m = 0; m < 8; m++) acc[m] = 0ull;

    const float* xrow = shl + rg * 8 * H_;
    #pragma unroll 2
    for (int h = 0; h < H_; h++) {
        u64 w2 = *((const u64*)sWb + h * 64 + gp);  // conflict-free LDS.64
        #pragma unroll
        for (int m = 0; m < 8; m++) {
            float xv = xrow[m * H_ + h];            // warp-broadcast
            ffma2(acc[m], w2, pack2(xv, xv));
        }
    }

    const size_t base = (size_t)k * B_ * N_ * H_ + ((size_t)b * N_ + i0 + rg * 8) * H_;
    #pragma unroll
    for (int m = 0; m < 8; m++) {
        float2 p = unpack2(acc[m]);
        __nv_bfloat16 hi0 = __float2bfloat16_rn(p.x);
        __nv_bfloat16 lo0 = __float2bfloat16_rn(p.x - __bfloat162float(hi0));
        __nv_bfloat16 hi1 = __float2bfloat16_rn(p.y);
        __nv_bfloat16 lo1 = __float2bfloat16_rn(p.y - __bfloat162float(hi1));
        g_t_hi[base + m * H_ + gp]      = hi0;
        g_t_lo[base + m * H_ + gp]      = lo0;
        g_t_hi[base + m * H_ + gp + 64] = hi1;
        g_t_lo[base + m * H_ + gp + 64] = lo1;
    }
}

// =====================================================================
// Kernel C: HMMA (mma.sync bf16) pairwise GEMM. 128x128 (i,j) tile, K=128.
//   out_k[i][j] = A_hi·B_hi + A_hi·B_lo + A_lo·B_hi  (A = t[k], B = hr)
//   6 smem planes, XOR-16B swizzle rows (256B/row) -> conflict-free LDSM.
//   8 warps = 2(m) x 4(n); warp tile 64 x 32; k0 staged to dead A0 planes.
// =====================================================================
#define PB 32768               // plane bytes: 128 rows x 256 B
#define PAIR_SMEM (6 * PB)     // 196608

// copy 128x128 bf16 row-major plane -> smem with XOR-16B swizzle
__device__ __forceinline__ void load_plane(char* dst, const __nv_bfloat16* src, int tid)
{
    const uint4* s = (const uint4*)src;
    #pragma unroll
    for (int it = 0; it < 8; it++) {
        int idx = tid + it * 256;               // 2048 x 16B
        int row = idx >> 4, c16 = idx & 15;
        uint32_t byte = row * 256 + ((c16 * 16) ^ ((row & 7) << 4));
        *(uint4*)(dst + byte) = s[idx];
    }
}

__global__ __launch_bounds__(256, 1)
void pair_kernel(const float* __restrict__ bbil, float2* __restrict__ out)
{
    extern __shared__ char smc[];
    const uint32_t sbase = smem_u32(smc);
    const int b  = blockIdx.z;
    const int i0 = blockIdx.y * 128;
    const int j0 = blockIdx.x * 128;
    const int tid = threadIdx.x;
    const int warp = tid >> 5, lane = tid & 31;
    const int wm = warp >> 2, wn = warp & 3;    // 2 x 4 warps

    // planes: 0 A0hi, 1 A0lo, 2 A1hi, 3 A1lo, 4 Bhi, 5 Blo
    const size_t arow = ((size_t)b * N_ + i0) * H_;
    const size_t brow = ((size_t)b * N_ + j0) * H_;
    load_plane(smc + 0 * PB, g_t_hi + arow, tid);
    load_plane(smc + 1 * PB, g_t_lo + arow, tid);
    load_plane(smc + 2 * PB, g_t_hi + (size_t)B_ * N_ * H_ + arow, tid);
    load_plane(smc + 3 * PB, g_t_lo + (size_t)B_ * N_ * H_ + arow, tid);
    load_plane(smc + 4 * PB, g_hr_hi + brow, tid);
    load_plane(smc + 5 * PB, g_hr_lo + brow, tid);
    __syncthreads();

    // per-lane ldmatrix geometry (row part fixed, col varies with ks)
    const int arowl = wm * 64 + ((lane >> 3) & 1) * 8 + (lane & 7);  // + mi*16
    const uint32_t acoff = (lane >> 4) * 16;
    const uint32_t asw = (arowl & 7) << 4;
    const uint32_t abase = (uint32_t)arowl * 256;

    const int l16 = lane & 15;
    const int browl = wn * 32 + (l16 & 7);                            // + ni*8
    const uint32_t bcoff = ((l16 >> 3) & 1) * 16;
    const uint32_t bsw = (browl & 7) << 4;
    const uint32_t bbase = (uint32_t)browl * 256;

    const uint32_t pBhi = sbase + 4 * PB, pBlo = sbase + 5 * PB;

    // output fragment geometry
    const int crow = lane >> 2;           // 0..7
    const int cj   = lane & 3;            // float2-pair index within n8
    float2* stage = (float2*)smc;         // reuses planes 0,1 after k0 passes

    const float bb0 = bbil[0], bb1 = bbil[1];

    for (int k = 0; k < 2; k++) {
        const uint32_t pAhi = sbase + (2 * k + 0) * PB;
        const uint32_t pAlo = sbase + (2 * k + 1) * PB;

        float acc[4][4][4];
        #pragma unroll
        for (int mi = 0; mi < 4; mi++)
            #pragma unroll
            for (int ni = 0; ni < 4; ni++)
                #pragma unroll
                for (int e = 0; e < 4; e++) acc[mi][ni][e] = 0.f;

        #pragma unroll 1
        for (int pass = 0; pass < 3; pass++) {
            const uint32_t pa = (pass == 2) ? pAlo : pAhi;
            const uint32_t pb = (pass == 1) ? pBlo : pBhi;
            #pragma unroll 4
            for (int ks = 0; ks < 8; ks++) {
                uint32_t a[4][4], bfr[4][2];
                #pragma unroll
                for (int mi = 0; mi < 4; mi++)
                    ldsm4(a[mi][0], a[mi][1], a[mi][2], a[mi][3],
                          pa + abase + mi * 4096 + (((uint32_t)ks * 32 + acoff) ^ asw));
                #pragma unroll
                for (int ni = 0; ni < 4; ni++)
                    ldsm2(bfr[ni][0], bfr[ni][1],
                          pb + bbase + ni * 2048 + (((uint32_t)ks * 32 + bcoff) ^ bsw));
                #pragma unroll
                for (int mi = 0; mi < 4; mi++)
                    #pragma unroll
                    for (int ni = 0; ni < 4; ni++)
                        mma_bf16(acc[mi][ni], a[mi], bfr[ni]);
            }
        }

        if (k == 0) {
            // A0 planes are dead now for THIS warp's rows, but other warps with the
            // same wm still read them -> sync before overwriting with staging.
            __syncthreads();
            #pragma unroll
            for (int mi = 0; mi < 4; mi++) {
                const int r = wm * 64 + mi * 16 + crow;
                #pragma unroll
                for (int ni = 0; ni < 4; ni++) {
                    const int j2 = wn * 16 + ni * 4 + cj;
                    stage[r * 64 + (j2 ^ ((r & 7) << 2))] =
                        make_float2(acc[mi][ni][0], acc[mi][ni][1]);
                    stage[(r + 8) * 64 + (j2 ^ (((r + 8) & 7) << 2))] =
                        make_float2(acc[mi][ni][2], acc[mi][ni][3]);
                }
            }
        } else {
            // combine staged k0 with k1 regs; float4 stores (two float2 out elems)
            #pragma unroll
            for (int mi = 0; mi < 4; mi++) {
                #pragma unroll
                for (int ni = 0; ni < 4; ni++) {
                    const int j2 = wn * 16 + ni * 4 + cj;
                    const int jj = j0 + j2 * 2;
                    {
                        const int r = wm * 64 + mi * 16 + crow;
                        float2 s = stage[r * 64 + (j2 ^ ((r & 7) << 2))];
                        float4 v = make_float4(s.x + bb0, acc[mi][ni][0] + bb1,
                                               s.y + bb0, acc[mi][ni][1] + bb1);
                        *(float4*)(out + ((size_t)b * N_ + i0 + r) * N_ + jj) = v;
                    }
                    {
                        const int r = wm * 64 + mi * 16 + crow + 8;
                        float2 s = stage[r * 64 + (j2 ^ ((r & 7) << 2))];
                        float4 v = make_float4(s.x + bb0, acc[mi][ni][2] + bb1,
                                               s.y + bb0, acc[mi][ni][3] + bb1);
                        *(float4*)(out + ((size_t)b * N_ + i0 + r) * N_ + jj) = v;
                    }
                }
            }
        }
    }
}

// =====================================================================
extern "C" void kernel_launch(void* const* d_in, const int* in_sizes, int n_in,
                              void* d_out, int out_size)
{
    (void)in_sizes; (void)n_in; (void)out_size;
    const float* x  = (const float*)d_in[0];
    const float* Wl = (const float*)d_in[1];
    const float* bl = (const float*)d_in[2];
    const float* Wr = (const float*)d_in[3];
    const float* br = (const float*)d_in[4];
    const float* Wb = (const float*)d_in[5];
    const float* bb = (const float*)d_in[6];

    const int smemA = (34 * NIN_ + H_ * WPITCH) * 4;    // 108,032 B
    const int smemB = (H_ * 64 * 2 + 32 * H_) * 4;      //  81,920 B
    const int smemC = PAIR_SMEM;                        // 196,608 B
    cudaFuncSetAttribute(hidden_kernel, cudaFuncAttributeMaxDynamicSharedMemorySize, smemA);
    cudaFuncSetAttribute(tform_kernel,  cudaFuncAttributeMaxDynamicSharedMemorySize, smemB);
    cudaFuncSetAttribute(pair_kernel,   cudaFuncAttributeMaxDynamicSharedMemorySize, smemC);

    hidden_kernel<<<dim3(N_ / 32, B_, 2), 256, smemA>>>(x, Wl, bl, Wr, br);
    tform_kernel <<<dim3(N_ / 32, B_, 2), 256, smemB>>>(Wb);
    pair_kernel  <<<dim3(8, 8, B_),       256, smemC>>>(bb, (float2*)d_out);
}

// round 9
// speedup vs baseline: 3.3420x; 1.0844x over previous
#include <cuda_runtime.h>
#include <cuda_bf16.h>
#include <cstdint>

#define B_   8
#define N_   1024
#define NIN_ 64
#define H_   128
#define F_   192

typedef unsigned long long u64;

// ---------------- f32x2 packed-FMA helpers ----------------
__device__ __forceinline__ u64 pack2(float x, float y) {
    u64 r; asm("mov.b64 %0, {%1, %2};" : "=l"(r) : "f"(x), "f"(y)); return r;
}
__device__ __forceinline__ float2 unpack2(u64 v) {
    float2 r; asm("mov.b64 {%0, %1}, %2;" : "=f"(r.x), "=f"(r.y) : "l"(v)); return r;
}
__device__ __forceinline__ void ffma2(u64& d, u64 a, u64 b) {
    asm("fma.rn.f32x2 %0, %1, %2, %0;" : "+l"(d) : "l"(a), "l"(b));
}

// ---------------- scratch (device globals) ----------------
__device__ float g_hl[B_ * N_ * H_];                               // 4 MB fp32
__device__ __align__(16) __nv_bfloat16 g_hr_hi[B_ * N_ * H_];      // 2 MB
__device__ __align__(16) __nv_bfloat16 g_hr_lo[B_ * N_ * H_];
__device__ __align__(16) __nv_bfloat16 g_t_hi[2 * B_ * N_ * H_];   // 4 MB (k planes)
__device__ __align__(16) __nv_bfloat16 g_t_lo[2 * B_ * N_ * H_];

__device__ __forceinline__ uint32_t smem_u32(const void* p) {
    uint32_t a;
    asm("{ .reg .u64 t; cvta.to.shared.u64 t, %1; cvt.u32.u64 %0, t; }" : "=r"(a) : "l"(p));
    return a;
}
// ---------------- tensor-core primitives (no 'a'-suffix PTX) ----------------
__device__ __forceinline__ void ldsm4(uint32_t& a0, uint32_t& a1, uint32_t& a2, uint32_t& a3, uint32_t addr) {
    asm volatile("ldmatrix.sync.aligned.m8n8.x4.shared.b16 {%0,%1,%2,%3}, [%4];"
        : "=r"(a0), "=r"(a1), "=r"(a2), "=r"(a3) : "r"(addr));
}
__device__ __forceinline__ void ldsm2(uint32_t& b0, uint32_t& b1, uint32_t addr) {
    asm volatile("ldmatrix.sync.aligned.m8n8.x2.shared.b16 {%0,%1}, [%2];"
        : "=r"(b0), "=r"(b1) : "r"(addr));
}
__device__ __forceinline__ void mma_bf16(float* c, const uint32_t* a, const uint32_t* b) {
    asm volatile("mma.sync.aligned.m16n8k16.row.col.f32.bf16.bf16.f32 "
        "{%0,%1,%2,%3}, {%4,%5,%6,%7}, {%8,%9}, {%0,%1,%2,%3};"
        : "+f"(c[0]), "+f"(c[1]), "+f"(c[2]), "+f"(c[3])
        : "r"(a[0]), "r"(a[1]), "r"(a[2]), "r"(a[3]), "r"(b[0]), "r"(b[1]));
}

// =====================================================================
// Kernel A v3: grid (32, 8, 4); z = side + 2*h_half. 64 h per block.
//   sWT[fp][h] = (W[h][2fp], W[h][2fp+1]) -> one LDS.128 per thread covers
//   2 h rows; x loads are warp-broadcast LDS.64. Thread tile: 2h x 4m.
//   smem 59.4 KB -> 3 CTAs/SM.
// =====================================================================
#define SWT_PITCH 66   // float2 pitch per fp row (64 h + 2 pad)

__global__ __launch_bounds__(256, 3)
void hidden_kernel(const float* __restrict__ x,
                   const float* __restrict__ Wl, const float* __restrict__ bl,
                   const float* __restrict__ Wr, const float* __restrict__ br)
{
    extern __shared__ float sm[];
    float* sx   = sm;                       // [34][64]
    float* sWTf = sm + 34 * NIN_;           // float2[96][SWT_PITCH] viewed as float

    const int b     = blockIdx.y;
    const int i0    = blockIdx.x * 32;
    const int side  = blockIdx.z & 1;
    const int hbase = (blockIdx.z >> 1) * 64;
    const int tid   = threadIdx.x;
    const float* xb = x + (size_t)b * N_ * NIN_;
    const float* W  = side ? Wr : Wl;

    for (int idx = tid; idx < 34 * NIN_; idx += 256) {
        int r = idx >> 6, c = idx & 63;
        int gi = i0 - 1 + r;
        sx[idx] = (gi >= 0 && gi < N_) ? xb[gi * NIN_ + c] : 0.f;
    }
    // W rows hbase..hbase+63 -> f-pair-transposed smem (coalesced global reads)
    for (int idx = tid; idx < 64 * F_; idx += 256) {
        int hl_ = idx / F_, f = idx % F_;
        sWTf[(f >> 1) * (2 * SWT_PITCH) + hl_ * 2 + (f & 1)] = W[(hbase + hl_) * F_ + f];
    }
    __syncthreads();

    const int hp = tid & 31;     // h-pair: h = hbase + 2hp (+1)
    const int rg = tid >> 5;     // 8 groups x 4 m rows (uniform per warp)

    u64 acc[4][2];
    #pragma unroll
    for (int m = 0; m < 4; m++) { acc[m][0] = 0ull; acc[m][1] = 0ull; }

    // xl = [x_i, x_{i-1}, x_{i+1}], xr = [x_i, x_{i+1}, x_{i-1}]; sx row r <-> i0-1+r
    #pragma unroll
    for (int seg = 0; seg < 3; seg++) {
        const int off = (seg == 0) ? 1 : ((seg == 1) == (side == 0) ? 0 : 2);
        const float* xs = sx + (off + rg * 4) * NIN_;
        const float* wp = sWTf + seg * 32 * (2 * SWT_PITCH) + hp * 4;
        #pragma unroll 4
        for (int fc2 = 0; fc2 < 32; fc2++) {
            ulonglong2 w = *(const ulonglong2*)(wp + fc2 * (2 * SWT_PITCH));
            #pragma unroll
            for (int m = 0; m < 4; m++) {
                u64 x2 = *(const u64*)(xs + m * NIN_ + fc2 * 2);   // broadcast
                ffma2(acc[m][0], w.x, x2);
                ffma2(acc[m][1], w.y, x2);
            }
        }
    }

    const int h0 = hbase + 2 * hp;
    const float bias0 = side ? br[h0] : bl[h0];
    const float bias1 = side ? br[h0 + 1] : bl[h0 + 1];
    const size_t rbase = (size_t)b * N_ + i0 + rg * 4;
    #pragma unroll
    for (int m = 0; m < 4; m++) {
        float2 p0 = unpack2(acc[m][0]);
        float2 p1 = unpack2(acc[m][1]);
        float v0 = fmaxf(p0.x + p0.y + bias0, 0.f);
        float v1 = fmaxf(p1.x + p1.y + bias1, 0.f);
        const size_t o = (rbase + m) * H_ + h0;
        if (side == 0) {
            *(float2*)(g_hl + o) = make_float2(v0, v1);
        } else {
            __nv_bfloat16 h0b = __float2bfloat16_rn(v0);
            __nv_bfloat16 h1b = __float2bfloat16_rn(v1);
            __nv_bfloat16 l0b = __float2bfloat16_rn(v0 - __bfloat162float(h0b));
            __nv_bfloat16 l1b = __float2bfloat16_rn(v1 - __bfloat162float(h1b));
            *(__nv_bfloat162*)(g_hr_hi + o) = __nv_bfloat162(h0b, h1b);
            *(__nv_bfloat162*)(g_hr_lo + o) = __nv_bfloat162(l0b, l1b);
        }
    }
}

// =====================================================================
// Kernel B v2: one k per block; hl transposed in smem so FFMA2 packs
//   m-pairs; w loaded as g-pair LDS.64. 15 instr per 8 FFMA2.
//   smem 84 KB -> 2 CTAs/SM.
// =====================================================================
__global__ __launch_bounds__(256, 2)
void tform_kernel(const float* __restrict__ Wbil)
{
    extern __shared__ float sm[];
    float* sWb  = sm;                 // [128][130]  (g contiguous)
    float* shlT = sm + H_ * 130;      // [128][34]   (h-major, m rows)

    const int b   = blockIdx.y;
    const int i0  = blockIdx.x * 32;
    const int k   = blockIdx.z;
    const int tid = threadIdx.x;
    const float* Wk = Wbil + (size_t)k * H_ * H_;

    for (int idx = tid; idx < H_ * H_; idx += 256) {
        int h = idx >> 7, g = idx & 127;
        sWb[h * 130 + g] = Wk[idx];
    }
    const float* hlp = g_hl + ((size_t)b * N_ + i0) * H_;
    for (int idx = tid; idx < 32 * H_; idx += 256) {
        int m = idx >> 7, h = idx & 127;
        shlT[h * 34 + m] = hlp[idx];
    }
    __syncthreads();

    const int gp = tid & 63;          // g-pair: g = 2gp (+1)
    const int rg = tid >> 6;          // 4 groups x 8 m rows (4 m-pairs)

    u64 acc[4][2];
    #pragma unroll
    for (int mp = 0; mp < 4; mp++) { acc[mp][0] = 0ull; acc[mp][1] = 0ull; }

    #pragma unroll 4
    for (int h = 0; h < H_; h++) {
        float2 wv = *(const float2*)(sWb + h * 130 + 2 * gp);  // conflict-free
        u64 w0 = pack2(wv.x, wv.x);
        u64 w1 = pack2(wv.y, wv.y);
        const float* xh = shlT + h * 34 + rg * 8;
        #pragma unroll
        for (int mp = 0; mp < 4; mp++) {
            u64 x2 = *(const u64*)(xh + 2 * mp);               // broadcast
            ffma2(acc[mp][0], w0, x2);
            ffma2(acc[mp][1], w1, x2);
        }
    }

    const size_t base = (size_t)k * B_ * N_ * H_ + ((size_t)b * N_ + i0 + rg * 8) * H_ + 2 * gp;
    #pragma unroll
    for (int mp = 0; mp < 4; mp++) {
        float2 p0 = unpack2(acc[mp][0]);   // (t[m0][2gp],   t[m1][2gp])
        float2 p1 = unpack2(acc[mp][1]);   // (t[m0][2gp+1], t[m1][2gp+1])
        // row m0 = 2mp
        {
            __nv_bfloat16 a = __float2bfloat16_rn(p0.x), c = __float2bfloat16_rn(p1.x);
            __nv_bfloat16 al = __float2bfloat16_rn(p0.x - __bfloat162float(a));
            __nv_bfloat16 cl = __float2bfloat16_rn(p1.x - __bfloat162float(c));
            *(__nv_bfloat162*)(g_t_hi + base + (2 * mp) * H_) = __nv_bfloat162(a, c);
            *(__nv_bfloat162*)(g_t_lo + base + (2 * mp) * H_) = __nv_bfloat162(al, cl);
        }
        // row m1 = 2mp+1
        {
            __nv_bfloat16 a = __float2bfloat16_rn(p0.y), c = __float2bfloat16_rn(p1.y);
            __nv_bfloat16 al = __float2bfloat16_rn(p0.y - __bfloat162float(a));
            __nv_bfloat16 cl = __float2bfloat16_rn(p1.y - __bfloat162float(c));
            *(__nv_bfloat162*)(g_t_hi + base + (2 * mp + 1) * H_) = __nv_bfloat162(a, c);
            *(__nv_bfloat162*)(g_t_lo + base + (2 * mp + 1) * H_) = __nv_bfloat162(al, cl);
        }
    }
}

// =====================================================================
// Kernel C v2: HMMA pairwise GEMM, both k accumulated in regs.
//   Per ks: B frags (hi+lo) loaded ONCE, reused for k0 & k1.
//   out_k = Ahi·Bhi + Ahi·Blo + Alo·Bhi.  No smem staging epilogue.
// =====================================================================
#define PB 32768               // plane bytes: 128 rows x 256 B
#define PAIR_SMEM (6 * PB)     // 196608

__device__ __forceinline__ void load_plane(char* dst, const __nv_bfloat16* src, int tid)
{
    const uint4* s = (const uint4*)src;
    #pragma unroll
    for (int it = 0; it < 8; it++) {
        int idx = tid + it * 256;               // 2048 x 16B
        int row = idx >> 4, c16 = idx & 15;
        uint32_t byte = row * 256 + ((c16 * 16) ^ ((row & 7) << 4));
        *(uint4*)(dst + byte) = s[idx];
    }
}

__global__ __launch_bounds__(256, 1)
void pair_kernel(const float* __restrict__ bbil, float2* __restrict__ out)
{
    extern __shared__ char smc[];
    const uint32_t sbase = smem_u32(smc);
    const int b  = blockIdx.z;
    const int i0 = blockIdx.y * 128;
    const int j0 = blockIdx.x * 128;
    const int tid = threadIdx.x;
    const int warp = tid >> 5, lane = tid & 31;
    const int wm = warp >> 2, wn = warp & 3;    // 2 x 4 warps

    // planes: 0 A0hi, 1 A0lo, 2 A1hi, 3 A1lo, 4 Bhi, 5 Blo
    const size_t arow = ((size_t)b * N_ + i0) * H_;
    const size_t brow = ((size_t)b * N_ + j0) * H_;
    load_plane(smc + 0 * PB, g_t_hi + arow, tid);
    load_plane(smc + 1 * PB, g_t_lo + arow, tid);
    load_plane(smc + 2 * PB, g_t_hi + (size_t)B_ * N_ * H_ + arow, tid);
    load_plane(smc + 3 * PB, g_t_lo + (size_t)B_ * N_ * H_ + arow, tid);
    load_plane(smc + 4 * PB, g_hr_hi + brow, tid);
    load_plane(smc + 5 * PB, g_hr_lo + brow, tid);
    __syncthreads();

    // ldmatrix geometry (identical to validated r7 layout)
    const int arowl = wm * 64 + ((lane >> 3) & 1) * 8 + (lane & 7);
    const uint32_t acoff = (lane >> 4) * 16;
    const uint32_t asw = (arowl & 7) << 4;
    const uint32_t abase = (uint32_t)arowl * 256;

    const int l16 = lane & 15;
    const int browl = wn * 32 + (l16 & 7);
    const uint32_t bcoff = ((l16 >> 3) & 1) * 16;
    const uint32_t bsw = (browl & 7) << 4;
    const uint32_t bbase = (uint32_t)browl * 256;

    const uint32_t pBhi = sbase + 4 * PB, pBlo = sbase + 5 * PB;

    float acc[2][4][4][4];
    #pragma unroll
    for (int k = 0; k < 2; k++)
        #pragma unroll
        for (int mi = 0; mi < 4; mi++)
            #pragma unroll
            for (int ni = 0; ni < 4; ni++)
                #pragma unroll
                for (int e = 0; e < 4; e++) acc[k][mi][ni][e] = 0.f;

    #pragma unroll 2
    for (int ks = 0; ks < 8; ks++) {
        const uint32_t kcol = (uint32_t)ks * 32;
        uint32_t bh[4][2], blf[4][2];
        #pragma unroll
        for (int ni = 0; ni < 4; ni++) {
            const uint32_t boff = bbase + ni * 2048 + ((kcol + bcoff) ^ bsw);
            ldsm2(bh[ni][0],  bh[ni][1],  pBhi + boff);
            ldsm2(blf[ni][0], blf[ni][1], pBlo + boff);
        }
        #pragma unroll
        for (int k = 0; k < 2; k++) {
            const uint32_t pAhi = sbase + (2 * k + 0) * PB;
            const uint32_t pAlo = sbase + (2 * k + 1) * PB;
            {
                uint32_t ah[4][4];
                #pragma unroll
                for (int mi = 0; mi < 4; mi++)
                    ldsm4(ah[mi][0], ah[mi][1], ah[mi][2], ah[mi][3],
                          pAhi + abase + mi * 4096 + ((kcol + acoff) ^ asw));
                #pragma unroll
                for (int mi = 0; mi < 4; mi++)
                    #pragma unroll
                    for (int ni = 0; ni < 4; ni++) {
                        mma_bf16(acc[k][mi][ni], ah[mi], bh[ni]);
                        mma_bf16(acc[k][mi][ni], ah[mi], blf[ni]);
                    }
            }
            {
                uint32_t al[4][4];
                #pragma unroll
                for (int mi = 0; mi < 4; mi++)
                    ldsm4(al[mi][0], al[mi][1], al[mi][2], al[mi][3],
                          pAlo + abase + mi * 4096 + ((kcol + acoff) ^ asw));
                #pragma unroll
                for (int mi = 0; mi < 4; mi++)
                    #pragma unroll
                    for (int ni = 0; ni < 4; ni++)
                        mma_bf16(acc[k][mi][ni], al[mi], bh[ni]);
            }
        }
    }

    // direct epilogue: float4 = (k0[c0]+b0, k1[c0]+b1, k0[c1]+b0, k1[c1]+b1)
    const float bb0 = bbil[0], bb1 = bbil[1];
    const int crow = lane >> 2;
    const int cj   = lane & 3;
    #pragma unroll
    for (int mi = 0; mi < 4; mi++) {
        #pragma unroll
        for (int ni = 0; ni < 4; ni++) {
            const int j2 = wn * 16 + ni * 4 + cj;
            const int jj = j0 + j2 * 2;
            {
                const int r = wm * 64 + mi * 16 + crow;
                float4 v = make_float4(acc[0][mi][ni][0] + bb0, acc[1][mi][ni][0] + bb1,
                                       acc[0][mi][ni][1] + bb0, acc[1][mi][ni][1] + bb1);
                *(float4*)(out + ((size_t)b * N_ + i0 + r) * N_ + jj) = v;
            }
            {
                const int r = wm * 64 + mi * 16 + crow + 8;
                float4 v = make_float4(acc[0][mi][ni][2] + bb0, acc[1][mi][ni][2] + bb1,
                                       acc[0][mi][ni][3] + bb0, acc[1][mi][ni][3] + bb1);
                *(float4*)(out + ((size_t)b * N_ + i0 + r) * N_ + jj) = v;
            }
        }
    }
}

// =====================================================================
extern "C" void kernel_launch(void* const* d_in, const int* in_sizes, int n_in,
                              void* d_out, int out_size)
{
    (void)in_sizes; (void)n_in; (void)out_size;
    const float* x  = (const float*)d_in[0];
    const float* Wl = (const float*)d_in[1];
    const float* bl = (const float*)d_in[2];
    const float* Wr = (const float*)d_in[3];
    const float* br = (const float*)d_in[4];
    const float* Wb = (const float*)d_in[5];
    const float* bb = (const float*)d_in[6];

    const int smemA = (34 * NIN_ + 96 * SWT_PITCH * 2) * 4;   //  59,392 B
    const int smemB = (H_ * 130 + H_ * 34) * 4;               //  83,968 B
    const int smemC = PAIR_SMEM;                              // 196,608 B
    cudaFuncSetAttribute(hidden_kernel, cudaFuncAttributeMaxDynamicSharedMemorySize, smemA);
    cudaFuncSetAttribute(tform_kernel,  cudaFuncAttributeMaxDynamicSharedMemorySize, smemB);
    cudaFuncSetAttribute(pair_kernel,   cudaFuncAttributeMaxDynamicSharedMemorySize, smemC);

    hidden_kernel<<<dim3(N_ / 32, B_, 4), 256, smemA>>>(x, Wl, bl, Wr, br);
    tform_kernel <<<dim3(N_ / 32, B_, 2), 256, smemB>>>(Wb);
    pair_kernel  <<<dim3(8, 8, B_),       256, smemC>>>(bb, (float2*)d_out);
}

// round 10
// speedup vs baseline: 5.0336x; 1.5062x over previous
#include <cuda_runtime.h>
#include <cuda_bf16.h>
#include <cstdint>

#define B_   8
#define N_   1024
#define NIN_ 64
#define H_   128
#define F_   192

typedef unsigned long long u64;

// ---------------- scratch (device globals) ----------------
// pre-swizzled bf16 weight planes (built by prep_kernel)
__device__ __align__(16) char g_Wsw_hi[2 * 49152];   // W sides, 384B-pitch swizzled
__device__ __align__(16) char g_Wsw_lo[2 * 49152];
__device__ __align__(16) char g_WbT_hi[2 * 32768];   // W_bil^T per k, 256B-pitch swizzled
__device__ __align__(16) char g_WbT_lo[2 * 32768];
// activations
__device__ __align__(16) __nv_bfloat16 g_hlb_hi[B_ * N_ * H_];     // 2 MB
__device__ __align__(16) __nv_bfloat16 g_hlb_lo[B_ * N_ * H_];
__device__ __align__(16) __nv_bfloat16 g_hr_hi[B_ * N_ * H_];
__device__ __align__(16) __nv_bfloat16 g_hr_lo[B_ * N_ * H_];
__device__ __align__(16) __nv_bfloat16 g_t_hi[2 * B_ * N_ * H_];   // 4 MB (k planes)
__device__ __align__(16) __nv_bfloat16 g_t_lo[2 * B_ * N_ * H_];

__device__ __forceinline__ uint32_t smem_u32(const void* p) {
    uint32_t a;
    asm("{ .reg .u64 t; cvta.to.shared.u64 t, %1; cvt.u32.u64 %0, t; }" : "=r"(a) : "l"(p));
    return a;
}
// ---------------- tensor-core primitives (no 'a'-suffix PTX) ----------------
__device__ __forceinline__ void ldsm4(uint32_t& a0, uint32_t& a1, uint32_t& a2, uint32_t& a3, uint32_t addr) {
    asm volatile("ldmatrix.sync.aligned.m8n8.x4.shared.b16 {%0,%1,%2,%3}, [%4];"
        : "=r"(a0), "=r"(a1), "=r"(a2), "=r"(a3) : "r"(addr));
}
__device__ __forceinline__ void ldsm2(uint32_t& b0, uint32_t& b1, uint32_t addr) {
    asm volatile("ldmatrix.sync.aligned.m8n8.x2.shared.b16 {%0,%1}, [%2];"
        : "=r"(b0), "=r"(b1) : "r"(addr));
}
__device__ __forceinline__ void mma_bf16(float* c, const uint32_t* a, const uint32_t* b) {
    asm volatile("mma.sync.aligned.m16n8k16.row.col.f32.bf16.bf16.f32 "
        "{%0,%1,%2,%3}, {%4,%5,%6,%7}, {%8,%9}, {%0,%1,%2,%3};"
        : "+f"(c[0]), "+f"(c[1]), "+f"(c[2]), "+f"(c[3])
        : "r"(a[0]), "r"(a[1]), "r"(a[2]), "r"(a[3]), "r"(b[0]), "r"(b[1]));
}
__device__ __forceinline__ void split_bf16(float v, __nv_bfloat16& hi, __nv_bfloat16& lo) {
    hi = __float2bfloat16_rn(v);
    lo = __float2bfloat16_rn(v - __bfloat162float(hi));
}

// =====================================================================
// prep: convert W matrices to bf16 hi/lo planes, PRE-SWIZZLED to the
//   smem image the GEMM kernels use (so they can memcpy linearly).
//   Region 1: Wl/Wr  [h][f], 384B pitch.  Region 2: W_bil^T [g][h], 256B pitch.
// =====================================================================
__global__ __launch_bounds__(256)
void prep_kernel(const float* __restrict__ Wl, const float* __restrict__ Wr,
                 const float* __restrict__ Wbil)
{
    const int t = blockIdx.x * 256 + threadIdx.x;
    if (t < 2 * H_ * F_) {                       // 49152
        int side = t / (H_ * F_), r = t % (H_ * F_);
        int h = r / F_, f = r % F_;
        float v = (side ? Wr : Wl)[r];
        __nv_bfloat16 hi, lo; split_bf16(v, hi, lo);
        uint32_t byte = (uint32_t)h * 384u + (((uint32_t)f * 2u) ^ (((uint32_t)h & 7u) << 4));
        *(__nv_bfloat16*)(g_Wsw_hi + side * 49152 + byte) = hi;
        *(__nv_bfloat16*)(g_Wsw_lo + side * 49152 + byte) = lo;
    } else if (t < 2 * H_ * F_ + 2 * H_ * H_) {  // + 32768
        int r = t - 2 * H_ * F_;
        int k = r / (H_ * H_), rr = r % (H_ * H_);
        int g = rr / H_, h = rr % H_;
        float v = Wbil[k * H_ * H_ + h * H_ + g];   // transpose read
        __nv_bfloat16 hi, lo; split_bf16(v, hi, lo);
        uint32_t byte = (uint32_t)g * 256u + (((uint32_t)h * 2u) ^ (((uint32_t)g & 7u) << 4));
        *(__nv_bfloat16*)(g_WbT_hi + k * 32768 + byte) = hi;
        *(__nv_bfloat16*)(g_WbT_lo + k * 32768 + byte) = lo;
    }
}

// =====================================================================
// Kernel A (HMMA): h[b,i0+m, h] = relu(bias[h] + sum_f A[m][f] * W[h][f])
//   A built from shifted x rows, bf16 hi/lo, 384B-pitch swizzled.
//   grid (8 i-tiles, 8 b, 2 side); m=128, n=128, k=192 (12 ks), 3 passes.
//   smem: Ahi|Alo|Bhi|Blo = 4 x 48KB = 192KB.
// =====================================================================
#define HP 49152    // 128 rows x 384 B

__global__ __launch_bounds__(256, 1)
void hidden_kernel(const float* __restrict__ x,
                   const float* __restrict__ bl, const float* __restrict__ br)
{
    extern __shared__ char smc[];
    const int i0   = blockIdx.x * 128;
    const int b    = blockIdx.y;
    const int side = blockIdx.z;
    const int tid  = threadIdx.x;

    // B: linear copy of pre-swizzled planes (48KB each = 3072 uint4)
    {
        const uint4* sh = (const uint4*)(g_Wsw_hi + side * HP);
        const uint4* sl = (const uint4*)(g_Wsw_lo + side * HP);
        uint4* dh = (uint4*)(smc + 2 * HP);
        uint4* dl = (uint4*)(smc + 3 * HP);
        #pragma unroll
        for (int it = 0; it < 12; it++) {
            dh[tid + it * 256] = sh[tid + it * 256];
            dl[tid + it * 256] = sl[tid + it * 256];
        }
    }
    // A: build from x with context shifts, convert to hi/lo
    const float* xb = x + (size_t)b * N_ * NIN_;
    #pragma unroll
    for (int seg = 0; seg < 3; seg++) {
        // seg0: x_i; seg1: side0->x_{i-1}, side1->x_{i+1}; seg2: opposite
        const int off = (seg == 0) ? 0 : (((seg == 1) == (side == 0)) ? -1 : 1);
        #pragma unroll 4
        for (int it = 0; it < 16; it++) {
            int idx = tid + it * 256;            // 128 rows x 32 col-pairs
            int m = idx >> 5, cp = idx & 31;
            int gi = i0 + m + off;
            float2 v = (gi >= 0 && gi < N_) ? *(const float2*)(xb + gi * NIN_ + cp * 2)
                                            : make_float2(0.f, 0.f);
            __nv_bfloat16 h0, l0, h1, l1;
            split_bf16(v.x, h0, l0); split_bf16(v.y, h1, l1);
            uint32_t byte = (uint32_t)m * 384u +
                (((uint32_t)(seg * 128 + cp * 4)) ^ (((uint32_t)m & 7u) << 4));
            *(__nv_bfloat162*)(smc + byte)      = __nv_bfloat162(h0, h1);
            *(__nv_bfloat162*)(smc + HP + byte) = __nv_bfloat162(l0, l1);
        }
    }
    __syncthreads();

    const int warp = tid >> 5, lane = tid & 31;
    const int wm = warp >> 2, wn = warp & 3;
    const int arowl = wm * 64 + ((lane >> 3) & 1) * 8 + (lane & 7);
    const uint32_t acoff = (lane >> 4) * 16;
    const uint32_t asw = (arowl & 7) << 4;
    const uint32_t abase = (uint32_t)arowl * 384;
    const int l16 = lane & 15;
    const int browl = wn * 32 + (l16 & 7);
    const uint32_t bcoff = ((l16 >> 3) & 1) * 16;
    const uint32_t bsw = (browl & 7) << 4;
    const uint32_t bbase = (uint32_t)browl * 384;

    const uint32_t sb = smem_u32(smc);
    const uint32_t pAhi = sb, pAlo = sb + HP, pBhi = sb + 2 * HP, pBlo = sb + 3 * HP;

    float acc[4][4][4];
    #pragma unroll
    for (int mi = 0; mi < 4; mi++)
        #pragma unroll
        for (int ni = 0; ni < 4; ni++)
            #pragma unroll
            for (int e = 0; e < 4; e++) acc[mi][ni][e] = 0.f;

    #pragma unroll 1
    for (int pass = 0; pass < 3; pass++) {
        const uint32_t pa = (pass == 2) ? pAlo : pAhi;
        const uint32_t pb = (pass == 1) ? pBlo : pBhi;
        #pragma unroll 4
        for (int ks = 0; ks < 12; ks++) {
            const uint32_t kcol = (uint32_t)ks * 32;
            uint32_t a[4][4], bf[4][2];
            #pragma unroll
            for (int mi = 0; mi < 4; mi++)
                ldsm4(a[mi][0], a[mi][1], a[mi][2], a[mi][3],
                      pa + abase + mi * 16 * 384 + ((kcol + acoff) ^ asw));
            #pragma unroll
            for (int ni = 0; ni < 4; ni++)
                ldsm2(bf[ni][0], bf[ni][1],
                      pb + bbase + ni * 8 * 384 + ((kcol + bcoff) ^ bsw));
            #pragma unroll
            for (int mi = 0; mi < 4; mi++)
                #pragma unroll
                for (int ni = 0; ni < 4; ni++)
                    mma_bf16(acc[mi][ni], a[mi], bf[ni]);
        }
    }

    // epilogue: relu + bias, split hi/lo, bfloat162 stores
    const int crow = lane >> 2, cj = lane & 3;
    const float* bias = side ? br : bl;
    __nv_bfloat16* dhi = side ? g_hr_hi : g_hlb_hi;
    __nv_bfloat16* dlo = side ? g_hr_lo : g_hlb_lo;
    #pragma unroll
    for (int mi = 0; mi < 4; mi++) {
        #pragma unroll
        for (int ni = 0; ni < 4; ni++) {
            const int h0 = wn * 32 + ni * 8 + 2 * cj;
            const float2 bv = *(const float2*)(bias + h0);
            #pragma unroll
            for (int half = 0; half < 2; half++) {
                const int r = wm * 64 + mi * 16 + crow + half * 8;
                float v0 = fmaxf(acc[mi][ni][2 * half + 0] + bv.x, 0.f);
                float v1 = fmaxf(acc[mi][ni][2 * half + 1] + bv.y, 0.f);
                __nv_bfloat16 h0b, l0b, h1b, l1b;
                split_bf16(v0, h0b, l0b); split_bf16(v1, h1b, l1b);
                const size_t o = ((size_t)b * N_ + i0 + r) * H_ + h0;
                *(__nv_bfloat162*)(dhi + o) = __nv_bfloat162(h0b, h1b);
                *(__nv_bfloat162*)(dlo + o) = __nv_bfloat162(l0b, l1b);
            }
        }
    }
}

// =====================================================================
// Kernel B (HMMA): t[k][b,i0+m, g] = sum_h hl[m][h] * WbT[k][g][h]
//   grid (8 i-tiles, 8 b, 2 k); m=128, n=128, k-dim=128 (8 ks), 3 passes.
//   smem: Ahi|Alo|Bhi|Blo = 4 x 32KB = 128KB. 256B-pitch swizzle.
// =====================================================================
#define PB 32768    // 128 rows x 256 B

__device__ __forceinline__ void load_plane(char* dst, const __nv_bfloat16* src, int tid)
{
    const uint4* s = (const uint4*)src;
    #pragma unroll
    for (int it = 0; it < 8; it++) {
        int idx = tid + it * 256;               // 2048 x 16B
        int row = idx >> 4, c16 = idx & 15;
        uint32_t byte = row * 256 + ((c16 * 16) ^ ((row & 7) << 4));
        *(uint4*)(dst + byte) = s[idx];
    }
}

__global__ __launch_bounds__(256, 1)
void tform_kernel()
{
    extern __shared__ char smc[];
    const int i0 = blockIdx.x * 128;
    const int b  = blockIdx.y;
    const int k  = blockIdx.z;
    const int tid = threadIdx.x;

    // A: hl hi/lo via swizzle-copy; B: linear copy of pre-swizzled WbT planes
    const size_t arow = ((size_t)b * N_ + i0) * H_;
    load_plane(smc + 0 * PB, g_hlb_hi + arow, tid);
    load_plane(smc + 1 * PB, g_hlb_lo + arow, tid);
    {
        const uint4* sh = (const uint4*)(g_WbT_hi + k * PB);
        const uint4* sl = (const uint4*)(g_WbT_lo + k * PB);
        uint4* dh = (uint4*)(smc + 2 * PB);
        uint4* dl = (uint4*)(smc + 3 * PB);
        #pragma unroll
        for (int it = 0; it < 8; it++) {
            dh[tid + it * 256] = sh[tid + it * 256];
            dl[tid + it * 256] = sl[tid + it * 256];
        }
    }
    __syncthreads();

    const int warp = tid >> 5, lane = tid & 31;
    const int wm = warp >> 2, wn = warp & 3;
    const int arowl = wm * 64 + ((lane >> 3) & 1) * 8 + (lane & 7);
    const uint32_t acoff = (lane >> 4) * 16;
    const uint32_t asw = (arowl & 7) << 4;
    const uint32_t abase = (uint32_t)arowl * 256;
    const int l16 = lane & 15;
    const int browl = wn * 32 + (l16 & 7);
    const uint32_t bcoff = ((l16 >> 3) & 1) * 16;
    const uint32_t bsw = (browl & 7) << 4;
    const uint32_t bbase = (uint32_t)browl * 256;

    const uint32_t sb = smem_u32(smc);
    const uint32_t pAhi = sb, pAlo = sb + PB, pBhi = sb + 2 * PB, pBlo = sb + 3 * PB;

    float acc[4][4][4];
    #pragma unroll
    for (int mi = 0; mi < 4; mi++)
        #pragma unroll
        for (int ni = 0; ni < 4; ni++)
            #pragma unroll
            for (int e = 0; e < 4; e++) acc[mi][ni][e] = 0.f;

    #pragma unroll 1
    for (int pass = 0; pass < 3; pass++) {
        const uint32_t pa = (pass == 2) ? pAlo : pAhi;
        const uint32_t pb = (pass == 1) ? pBlo : pBhi;
        #pragma unroll 4
        for (int ks = 0; ks < 8; ks++) {
            const uint32_t kcol = (uint32_t)ks * 32;
            uint32_t a[4][4], bf[4][2];
            #pragma unroll
            for (int mi = 0; mi < 4; mi++)
                ldsm4(a[mi][0], a[mi][1], a[mi][2], a[mi][3],
                      pa + abase + mi * 4096 + ((kcol + acoff) ^ asw));
            #pragma unroll
            for (int ni = 0; ni < 4; ni++)
                ldsm2(bf[ni][0], bf[ni][1],
                      pb + bbase + ni * 2048 + ((kcol + bcoff) ^ bsw));
            #pragma unroll
            for (int mi = 0; mi < 4; mi++)
                #pragma unroll
                for (int ni = 0; ni < 4; ni++)
                    mma_bf16(acc[mi][ni], a[mi], bf[ni]);
        }
    }

    // epilogue: split to hi/lo, store to g_t planes
    const int crow = lane >> 2, cj = lane & 3;
    __nv_bfloat16* dhi = g_t_hi + (size_t)k * B_ * N_ * H_;
    __nv_bfloat16* dlo = g_t_lo + (size_t)k * B_ * N_ * H_;
    #pragma unroll
    for (int mi = 0; mi < 4; mi++) {
        #pragma unroll
        for (int ni = 0; ni < 4; ni++) {
            const int g0 = wn * 32 + ni * 8 + 2 * cj;
            #pragma unroll
            for (int half = 0; half < 2; half++) {
                const int r = wm * 64 + mi * 16 + crow + half * 8;
                float v0 = acc[mi][ni][2 * half + 0];
                float v1 = acc[mi][ni][2 * half + 1];
                __nv_bfloat16 h0b, l0b, h1b, l1b;
                split_bf16(v0, h0b, l0b); split_bf16(v1, h1b, l1b);
                const size_t o = ((size_t)b * N_ + i0 + r) * H_ + g0;
                *(__nv_bfloat162*)(dhi + o) = __nv_bfloat162(h0b, h1b);
                *(__nv_bfloat162*)(dlo + o) = __nv_bfloat162(l0b, l1b);
            }
        }
    }
}

// =====================================================================
// Kernel C: HMMA pairwise GEMM (UNCHANGED from r9 — passing & validated).
// =====================================================================
#define PAIR_SMEM (6 * PB)     // 196608

__global__ __launch_bounds__(256, 1)
void pair_kernel(const float* __restrict__ bbil, float2* __restrict__ out)
{
    extern __shared__ char smc[];
    const uint32_t sbase = smem_u32(smc);
    const int b  = blockIdx.z;
    const int i0 = blockIdx.y * 128;
    const int j0 = blockIdx.x * 128;
    const int tid = threadIdx.x;
    const int warp = tid >> 5, lane = tid & 31;
    const int wm = warp >> 2, wn = warp & 3;

    const size_t arow = ((size_t)b * N_ + i0) * H_;
    const size_t brow = ((size_t)b * N_ + j0) * H_;
    load_plane(smc + 0 * PB, g_t_hi + arow, tid);
    load_plane(smc + 1 * PB, g_t_lo + arow, tid);
    load_plane(smc + 2 * PB, g_t_hi + (size_t)B_ * N_ * H_ + arow, tid);
    load_plane(smc + 3 * PB, g_t_lo + (size_t)B_ * N_ * H_ + arow, tid);
    load_plane(smc + 4 * PB, g_hr_hi + brow, tid);
    load_plane(smc + 5 * PB, g_hr_lo + brow, tid);
    __syncthreads();

    const int arowl = wm * 64 + ((lane >> 3) & 1) * 8 + (lane & 7);
    const uint32_t acoff = (lane >> 4) * 16;
    const uint32_t asw = (arowl & 7) << 4;
    const uint32_t abase = (uint32_t)arowl * 256;
    const int l16 = lane & 15;
    const int browl = wn * 32 + (l16 & 7);
    const uint32_t bcoff = ((l16 >> 3) & 1) * 16;
    const uint32_t bsw = (browl & 7) << 4;
    const uint32_t bbase = (uint32_t)browl * 256;

    const uint32_t pBhi = sbase + 4 * PB, pBlo = sbase + 5 * PB;

    float acc[2][4][4][4];
    #pragma unroll
    for (int k = 0; k < 2; k++)
        #pragma unroll
        for (int mi = 0; mi < 4; mi++)
            #pragma unroll
            for (int ni = 0; ni < 4; ni++)
                #pragma unroll
                for (int e = 0; e < 4; e++) acc[k][mi][ni][e] = 0.f;

    #pragma unroll 2
    for (int ks = 0; ks < 8; ks++) {
        const uint32_t kcol = (uint32_t)ks * 32;
        uint32_t bh[4][2], blf[4][2];
        #pragma unroll
        for (int ni = 0; ni < 4; ni++) {
            const uint32_t boff = bbase + ni * 2048 + ((kcol + bcoff) ^ bsw);
            ldsm2(bh[ni][0],  bh[ni][1],  pBhi + boff);
            ldsm2(blf[ni][0], blf[ni][1], pBlo + boff);
        }
        #pragma unroll
        for (int k = 0; k < 2; k++) {
            const uint32_t pAhi = sbase + (2 * k + 0) * PB;
            const uint32_t pAlo = sbase + (2 * k + 1) * PB;
            {
                uint32_t ah[4][4];
                #pragma unroll
                for (int mi = 0; mi < 4; mi++)
                    ldsm4(ah[mi][0], ah[mi][1], ah[mi][2], ah[mi][3],
                          pAhi + abase + mi * 4096 + ((kcol + acoff) ^ asw));
                #pragma unroll
                for (int mi = 0; mi < 4; mi++)
                    #pragma unroll
                    for (int ni = 0; ni < 4; ni++) {
                        mma_bf16(acc[k][mi][ni], ah[mi], bh[ni]);
                        mma_bf16(acc[k][mi][ni], ah[mi], blf[ni]);
                    }
            }
            {
                uint32_t al[4][4];
                #pragma unroll
                for (int mi = 0; mi < 4; mi++)
                    ldsm4(al[mi][0], al[mi][1], al[mi][2], al[mi][3],
                          pAlo + abase + mi * 4096 + ((kcol + acoff) ^ asw));
                #pragma unroll
                for (int mi = 0; mi < 4; mi++)
                    #pragma unroll
                    for (int ni = 0; ni < 4; ni++)
                        mma_bf16(acc[k][mi][ni], al[mi], bh[ni]);
            }
        }
    }

    const float bb0 = bbil[0], bb1 = bbil[1];
    const int crow = lane >> 2;
    const int cj   = lane & 3;
    #pragma unroll
    for (int mi = 0; mi < 4; mi++) {
        #pragma unroll
        for (int ni = 0; ni < 4; ni++) {
            const int j2 = wn * 16 + ni * 4 + cj;
            const int jj = j0 + j2 * 2;
            {
                const int r = wm * 64 + mi * 16 + crow;
                float4 v = make_float4(acc[0][mi][ni][0] + bb0, acc[1][mi][ni][0] + bb1,
                                       acc[0][mi][ni][1] + bb0, acc[1][mi][ni][1] + bb1);
                *(float4*)(out + ((size_t)b * N_ + i0 + r) * N_ + jj) = v;
            }
            {
                const int r = wm * 64 + mi * 16 + crow + 8;
                float4 v = make_float4(acc[0][mi][ni][2] + bb0, acc[1][mi][ni][2] + bb1,
                                       acc[0][mi][ni][3] + bb0, acc[1][mi][ni][3] + bb1);
                *(float4*)(out + ((size_t)b * N_ + i0 + r) * N_ + jj) = v;
            }
        }
    }
}

// =====================================================================
extern "C" void kernel_launch(void* const* d_in, const int* in_sizes, int n_in,
                              void* d_out, int out_size)
{
    (void)in_sizes; (void)n_in; (void)out_size;
    const float* x  = (const float*)d_in[0];
    const float* Wl = (const float*)d_in[1];
    const float* bl = (const float*)d_in[2];
    const float* Wr = (const float*)d_in[3];
    const float* br = (const float*)d_in[4];
    const float* Wb = (const float*)d_in[5];
    const float* bb = (const float*)d_in[6];

    const int smemH = 4 * HP;        // 196,608 B
    const int smemT = 4 * PB;        // 131,072 B
    const int smemC = PAIR_SMEM;     // 196,608 B
    cudaFuncSetAttribute(hidden_kernel, cudaFuncAttributeMaxDynamicSharedMemorySize, smemH);
    cudaFuncSetAttribute(tform_kernel,  cudaFuncAttributeMaxDynamicSharedMemorySize, smemT);
    cudaFuncSetAttribute(pair_kernel,   cudaFuncAttributeMaxDynamicSharedMemorySize, smemC);

    prep_kernel  <<<320, 256>>>(Wl, Wr, Wb);
    hidden_kernel<<<dim3(8, B_, 2), 256, smemH>>>(x, bl, br);
    tform_kernel <<<dim3(8, B_, 2), 256, smemT>>>();
    pair_kernel  <<<dim3(8, 8, B_), 256, smemC>>>(bb, (float2*)d_out);
}

// round 13
// speedup vs baseline: 5.6481x; 1.1221x over previous
#include <cuda_runtime.h>
#include <cuda_bf16.h>
#include <cstdint>

#define B_   8
#define N_   1024
#define NIN_ 64
#define H_   128
#define F_   192

typedef unsigned long long u64;

// ---------------- scratch (device globals) ----------------
__device__ __align__(16) char g_Wsw_hi[2 * 49152];   // W sides, 384B-pitch swizzled
__device__ __align__(16) char g_Wsw_lo[2 * 49152];
__device__ __align__(16) char g_WbT_hi[2 * 32768];   // W_bil^T per k, 256B-pitch swizzled
__device__ __align__(16) char g_WbT_lo[2 * 32768];
__device__ __align__(16) __nv_bfloat16 g_hlb_hi[B_ * N_ * H_];
__device__ __align__(16) __nv_bfloat16 g_hlb_lo[B_ * N_ * H_];
__device__ __align__(16) __nv_bfloat16 g_hr_hi[B_ * N_ * H_];
__device__ __align__(16) __nv_bfloat16 g_hr_lo[B_ * N_ * H_];
__device__ __align__(16) __nv_bfloat16 g_t_hi[2 * B_ * N_ * H_];
__device__ __align__(16) __nv_bfloat16 g_t_lo[2 * B_ * N_ * H_];

__device__ __forceinline__ uint32_t smem_u32(const void* p) {
    uint32_t a;
    asm("{ .reg .u64 t; cvta.to.shared.u64 t, %1; cvt.u32.u64 %0, t; }" : "=r"(a) : "l"(p));
    return a;
}
// ---------------- tensor-core primitives (no 'a'-suffix PTX) ----------------
__device__ __forceinline__ void ldsm4(uint32_t& a0, uint32_t& a1, uint32_t& a2, uint32_t& a3, uint32_t addr) {
    asm volatile("ldmatrix.sync.aligned.m8n8.x4.shared.b16 {%0,%1,%2,%3}, [%4];"
        : "=r"(a0), "=r"(a1), "=r"(a2), "=r"(a3) : "r"(addr));
}
__device__ __forceinline__ void ldsm2(uint32_t& b0, uint32_t& b1, uint32_t addr) {
    asm volatile("ldmatrix.sync.aligned.m8n8.x2.shared.b16 {%0,%1}, [%2];"
        : "=r"(b0), "=r"(b1) : "r"(addr));
}
__device__ __forceinline__ void mma_bf16(float* c, const uint32_t* a, const uint32_t* b) {
    asm volatile("mma.sync.aligned.m16n8k16.row.col.f32.bf16.bf16.f32 "
        "{%0,%1,%2,%3}, {%4,%5,%6,%7}, {%8,%9}, {%0,%1,%2,%3};"
        : "+f"(c[0]), "+f"(c[1]), "+f"(c[2]), "+f"(c[3])
        : "r"(a[0]), "r"(a[1]), "r"(a[2]), "r"(a[3]), "r"(b[0]), "r"(b[1]));
}
__device__ __forceinline__ void split_bf16(float v, __nv_bfloat16& hi, __nv_bfloat16& lo) {
    hi = __float2bfloat16_rn(v);
    lo = __float2bfloat16_rn(v - __bfloat162float(hi));
}
// ---------------- cp.async ----------------
__device__ __forceinline__ void cp16(uint32_t dst, const void* src) {
    asm volatile("cp.async.cg.shared.global [%0], [%1], 16;" :: "r"(dst), "l"(src));
}
__device__ __forceinline__ void cp_commit() { asm volatile("cp.async.commit_group;" ::: "memory"); }
__device__ __forceinline__ void cp_wait0()  { asm volatile("cp.async.wait_group 0;" ::: "memory"); }

// =====================================================================
// prep: W -> bf16 hi/lo planes, pre-swizzled (unchanged from r10)
// =====================================================================
__global__ __launch_bounds__(256)
void prep_kernel(const float* __restrict__ Wl, const float* __restrict__ Wr,
                 const float* __restrict__ Wbil)
{
    const int t = blockIdx.x * 256 + threadIdx.x;
    if (t < 2 * H_ * F_) {
        int side = t / (H_ * F_), r = t % (H_ * F_);
        int h = r / F_, f = r % F_;
        float v = (side ? Wr : Wl)[r];
        __nv_bfloat16 hi, lo; split_bf16(v, hi, lo);
        uint32_t byte = (uint32_t)h * 384u + (((uint32_t)f * 2u) ^ (((uint32_t)h & 7u) << 4));
        *(__nv_bfloat16*)(g_Wsw_hi + side * 49152 + byte) = hi;
        *(__nv_bfloat16*)(g_Wsw_lo + side * 49152 + byte) = lo;
    } else if (t < 2 * H_ * F_ + 2 * H_ * H_) {
        int r = t - 2 * H_ * F_;
        int k = r / (H_ * H_), rr = r % (H_ * H_);
        int g = rr / H_, h = rr % H_;
        float v = Wbil[k * H_ * H_ + h * H_ + g];
        __nv_bfloat16 hi, lo; split_bf16(v, hi, lo);
        uint32_t byte = (uint32_t)g * 256u + (((uint32_t)h * 2u) ^ (((uint32_t)g & 7u) << 4));
        *(__nv_bfloat16*)(g_WbT_hi + k * 32768 + byte) = hi;
        *(__nv_bfloat16*)(g_WbT_lo + k * 32768 + byte) = lo;
    }
}

// =====================================================================
// Kernel A (HMMA, unchanged from r10)
// =====================================================================
#define HP 49152

__global__ __launch_bounds__(256, 1)
void hidden_kernel(const float* __restrict__ x,
                   const float* __restrict__ bl, const float* __restrict__ br)
{
    extern __shared__ char smc[];
    const int i0   = blockIdx.x * 128;
    const int b    = blockIdx.y;
    const int side = blockIdx.z;
    const int tid  = threadIdx.x;

    {
        const uint4* sh = (const uint4*)(g_Wsw_hi + side * HP);
        const uint4* sl = (const uint4*)(g_Wsw_lo + side * HP);
        uint4* dh = (uint4*)(smc + 2 * HP);
        uint4* dl = (uint4*)(smc + 3 * HP);
        #pragma unroll
        for (int it = 0; it < 12; it++) {
            dh[tid + it * 256] = sh[tid + it * 256];
            dl[tid + it * 256] = sl[tid + it * 256];
        }
    }
    const float* xb = x + (size_t)b * N_ * NIN_;
    #pragma unroll
    for (int seg = 0; seg < 3; seg++) {
        const int off = (seg == 0) ? 0 : (((seg == 1) == (side == 0)) ? -1 : 1);
        #pragma unroll 4
        for (int it = 0; it < 16; it++) {
            int idx = tid + it * 256;
            int m = idx >> 5, cp = idx & 31;
            int gi = i0 + m + off;
            float2 v = (gi >= 0 && gi < N_) ? *(const float2*)(xb + gi * NIN_ + cp * 2)
                                            : make_float2(0.f, 0.f);
            __nv_bfloat16 h0, l0, h1, l1;
            split_bf16(v.x, h0, l0); split_bf16(v.y, h1, l1);
            uint32_t byte = (uint32_t)m * 384u +
                (((uint32_t)(seg * 128 + cp * 4)) ^ (((uint32_t)m & 7u) << 4));
            *(__nv_bfloat162*)(smc + byte)      = __nv_bfloat162(h0, h1);
            *(__nv_bfloat162*)(smc + HP + byte) = __nv_bfloat162(l0, l1);
        }
    }
    __syncthreads();

    const int warp = tid >> 5, lane = tid & 31;
    const int wm = warp >> 2, wn = warp & 3;
    const int arowl = wm * 64 + ((lane >> 3) & 1) * 8 + (lane & 7);
    const uint32_t acoff = (lane >> 4) * 16;
    const uint32_t asw = (arowl & 7) << 4;
    const uint32_t abase = (uint32_t)arowl * 384;
    const int l16 = lane & 15;
    const int browl = wn * 32 + (l16 & 7);
    const uint32_t bcoff = ((l16 >> 3) & 1) * 16;
    const uint32_t bsw = (browl & 7) << 4;
    const uint32_t bbase = (uint32_t)browl * 384;

    const uint32_t sb = smem_u32(smc);
    const uint32_t pAhi = sb, pAlo = sb + HP, pBhi = sb + 2 * HP, pBlo = sb + 3 * HP;

    float acc[4][4][4];
    #pragma unroll
    for (int mi = 0; mi < 4; mi++)
        #pragma unroll
        for (int ni = 0; ni < 4; ni++)
            #pragma unroll
            for (int e = 0; e < 4; e++) acc[mi][ni][e] = 0.f;

    #pragma unroll 1
    for (int pass = 0; pass < 3; pass++) {
        const uint32_t pa = (pass == 2) ? pAlo : pAhi;
        const uint32_t pb = (pass == 1) ? pBlo : pBhi;
        #pragma unroll 4
        for (int ks = 0; ks < 12; ks++) {
            const uint32_t kcol = (uint32_t)ks * 32;
            uint32_t a[4][4], bf[4][2];
            #pragma unroll
            for (int mi = 0; mi < 4; mi++)
                ldsm4(a[mi][0], a[mi][1], a[mi][2], a[mi][3],
                      pa + abase + mi * 16 * 384 + ((kcol + acoff) ^ asw));
            #pragma unroll
            for (int ni = 0; ni < 4; ni++)
                ldsm2(bf[ni][0], bf[ni][1],
                      pb + bbase + ni * 8 * 384 + ((kcol + bcoff) ^ bsw));
            #pragma unroll
            for (int mi = 0; mi < 4; mi++)
                #pragma unroll
                for (int ni = 0; ni < 4; ni++)
                    mma_bf16(acc[mi][ni], a[mi], bf[ni]);
        }
    }

    const int crow = lane >> 2, cj = lane & 3;
    const float* bias = side ? br : bl;
    __nv_bfloat16* dhi = side ? g_hr_hi : g_hlb_hi;
    __nv_bfloat16* dlo = side ? g_hr_lo : g_hlb_lo;
    #pragma unroll
    for (int mi = 0; mi < 4; mi++) {
        #pragma unroll
        for (int ni = 0; ni < 4; ni++) {
            const int h0 = wn * 32 + ni * 8 + 2 * cj;
            const float2 bv = *(const float2*)(bias + h0);
            #pragma unroll
            for (int half = 0; half < 2; half++) {
                const int r = wm * 64 + mi * 16 + crow + half * 8;
                float v0 = fmaxf(acc[mi][ni][2 * half + 0] + bv.x, 0.f);
                float v1 = fmaxf(acc[mi][ni][2 * half + 1] + bv.y, 0.f);
                __nv_bfloat16 h0b, l0b, h1b, l1b;
                split_bf16(v0, h0b, l0b); split_bf16(v1, h1b, l1b);
                const size_t o = ((size_t)b * N_ + i0 + r) * H_ + h0;
                *(__nv_bfloat162*)(dhi + o) = __nv_bfloat162(h0b, h1b);
                *(__nv_bfloat162*)(dlo + o) = __nv_bfloat162(l0b, l1b);
            }
        }
    }
}

// =====================================================================
// Kernel B (HMMA, unchanged from r10)
// =====================================================================
#define PB 32768

__device__ __forceinline__ void load_plane(char* dst, const __nv_bfloat16* src, int tid)
{
    const uint4* s = (const uint4*)src;
    #pragma unroll
    for (int it = 0; it < 8; it++) {
        int idx = tid + it * 256;
        int row = idx >> 4, c16 = idx & 15;
        uint32_t byte = row * 256 + ((c16 * 16) ^ ((row & 7) << 4));
        *(uint4*)(dst + byte) = s[idx];
    }
}

__global__ __launch_bounds__(256, 1)
void tform_kernel()
{
    extern __shared__ char smc[];
    const int i0 = blockIdx.x * 128;
    const int b  = blockIdx.y;
    const int k  = blockIdx.z;
    const int tid = threadIdx.x;

    const size_t arow = ((size_t)b * N_ + i0) * H_;
    load_plane(smc + 0 * PB, g_hlb_hi + arow, tid);
    load_plane(smc + 1 * PB, g_hlb_lo + arow, tid);
    {
        const uint4* sh = (const uint4*)(g_WbT_hi + k * PB);
        const uint4* sl = (const uint4*)(g_WbT_lo + k * PB);
        uint4* dh = (uint4*)(smc + 2 * PB);
        uint4* dl = (uint4*)(smc + 3 * PB);
        #pragma unroll
        for (int it = 0; it < 8; it++) {
            dh[tid + it * 256] = sh[tid + it * 256];
            dl[tid + it * 256] = sl[tid + it * 256];
        }
    }
    __syncthreads();

    const int warp = tid >> 5, lane = tid & 31;
    const int wm = warp >> 2, wn = warp & 3;
    const int arowl = wm * 64 + ((lane >> 3) & 1) * 8 + (lane & 7);
    const uint32_t acoff = (lane >> 4) * 16;
    const uint32_t asw = (arowl & 7) << 4;
    const uint32_t abase = (uint32_t)arowl * 256;
    const int l16 = lane & 15;
    const int browl = wn * 32 + (l16 & 7);
    const uint32_t bcoff = ((l16 >> 3) & 1) * 16;
    const uint32_t bsw = (browl & 7) << 4;
    const uint32_t bbase = (uint32_t)browl * 256;

    const uint32_t sb = smem_u32(smc);
    const uint32_t pAhi = sb, pAlo = sb + PB, pBhi = sb + 2 * PB, pBlo = sb + 3 * PB;

    float acc[4][4][4];
    #pragma unroll
    for (int mi = 0; mi < 4; mi++)
        #pragma unroll
        for (int ni = 0; ni < 4; ni++)
            #pragma unroll
            for (int e = 0; e < 4; e++) acc[mi][ni][e] = 0.f;

    #pragma unroll 1
    for (int pass = 0; pass < 3; pass++) {
        const uint32_t pa = (pass == 2) ? pAlo : pAhi;
        const uint32_t pb = (pass == 1) ? pBlo : pBhi;
        #pragma unroll 4
        for (int ks = 0; ks < 8; ks++) {
            const uint32_t kcol = (uint32_t)ks * 32;
            uint32_t a[4][4], bf[4][2];
            #pragma unroll
            for (int mi = 0; mi < 4; mi++)
                ldsm4(a[mi][0], a[mi][1], a[mi][2], a[mi][3],
                      pa + abase + mi * 4096 + ((kcol + acoff) ^ asw));
            #pragma unroll
            for (int ni = 0; ni < 4; ni++)
                ldsm2(bf[ni][0], bf[ni][1],
                      pb + bbase + ni * 2048 + ((kcol + bcoff) ^ bsw));
            #pragma unroll
            for (int mi = 0; mi < 4; mi++)
                #pragma unroll
                for (int ni = 0; ni < 4; ni++)
                    mma_bf16(acc[mi][ni], a[mi], bf[ni]);
        }
    }

    const int crow = lane >> 2, cj = lane & 3;
    __nv_bfloat16* dhi = g_t_hi + (size_t)k * B_ * N_ * H_;
    __nv_bfloat16* dlo = g_t_lo + (size_t)k * B_ * N_ * H_;
    #pragma unroll
    for (int mi = 0; mi < 4; mi++) {
        #pragma unroll
        for (int ni = 0; ni < 4; ni++) {
            const int g0 = wn * 32 + ni * 8 + 2 * cj;
            #pragma unroll
            for (int half = 0; half < 2; half++) {
                const int r = wm * 64 + mi * 16 + crow + half * 8;
                float v0 = acc[mi][ni][2 * half + 0];
                float v1 = acc[mi][ni][2 * half + 1];
                __nv_bfloat16 h0b, l0b, h1b, l1b;
                split_bf16(v0, h0b, l0b); split_bf16(v1, h1b, l1b);
                const size_t o = ((size_t)b * N_ + i0 + r) * H_ + g0;
                *(__nv_bfloat162*)(dhi + o) = __nv_bfloat162(h0b, h1b);
                *(__nv_bfloat162*)(dlo + o) = __nv_bfloat162(l0b, l1b);
            }
        }
    }
}

// =====================================================================
// Kernel C v3: persistent pipelined pair GEMM.
//   Grid 128 CTAs = (8 j-tiles, 8 b, 2 i-halves) -> one wave.
//   B (hr hi/lo, 64KB) resident; A chunks (64 i-rows x k0/k1 x hi/lo, 64KB)
//   double-buffered via cp.async, overlapping loads with HMMA compute.
//   smem: B 64KB @0, Abuf0 64KB @65536, Abuf1 @131072 -> 192KB.
// =====================================================================
#define PAIR_SMEM 196608
#define SUBP 16384            // 64 rows x 256B sub-plane

__device__ __forceinline__ void issue_A_chunk(uint32_t dstbase, int b, int i0c, int tid)
{
    const size_t bnh = (size_t)B_ * N_ * H_;
    const size_t rowbase = ((size_t)b * N_ + i0c) * H_;
    #pragma unroll
    for (int it = 0; it < 16; it++) {
        int idx = tid + it * 256;                 // 4096 x 16B
        int sub = idx >> 10;                      // 0..3 : k0hi,k0lo,k1hi,k1lo
        int k = sub >> 1, p = sub & 1;
        int r = (idx >> 4) & 63, c16 = idx & 15;
        const __nv_bfloat16* src = (p ? g_t_lo : g_t_hi) + k * bnh + rowbase + (size_t)r * H_ + c16 * 8;
        uint32_t dst = dstbase + sub * SUBP + r * 256 + ((c16 * 16) ^ ((r & 7) << 4));
        cp16(dst, src);
    }
}

__global__ __launch_bounds__(256, 1)
void pair_kernel(const float* __restrict__ bbil, float2* __restrict__ out)
{
    extern __shared__ char smc[];
    const uint32_t sbase = smem_u32(smc);
    const int j0    = blockIdx.x * 128;
    const int b     = blockIdx.y;
    const int ihalf = blockIdx.z;
    const int tid = threadIdx.x;
    const int warp = tid >> 5, lane = tid & 31;
    const int wm = warp >> 2, wn = warp & 3;     // 2(m) x 4(n)

    // --- B planes (hr hi/lo) via cp.async, swizzled ---
    {
        #pragma unroll
        for (int it = 0; it < 16; it++) {
            int idx = tid + it * 256;             // 4096 x 16B
            int p = idx >> 11;                    // 0 hi, 1 lo
            int r = (idx >> 4) & 127, c16 = idx & 15;
            const __nv_bfloat16* src = (p ? g_hr_lo : g_hr_hi) + ((size_t)b * N_ + j0 + r) * H_ + c16 * 8;
            uint32_t dst = sbase + p * PB + r * 256 + ((c16 * 16) ^ ((r & 7) << 4));
            cp16(dst, src);
        }
    }
    // --- prefetch A chunk 0 ---
    issue_A_chunk(sbase + 65536, b, ihalf * 512, tid);
    cp_commit();

    // lane geometry
    const int arowl = wm * 32 + ((lane >> 3) & 1) * 8 + (lane & 7);   // + mi*16
    const uint32_t acoff = (lane >> 4) * 16;
    const uint32_t asw = (arowl & 7) << 4;
    const uint32_t abase = (uint32_t)arowl * 256;
    const int l16 = lane & 15;
    const int browl = wn * 32 + (l16 & 7);                             // + ni*8
    const uint32_t bcoff = ((l16 >> 3) & 1) * 16;
    const uint32_t bsw = (browl & 7) << 4;
    const uint32_t bbase = (uint32_t)browl * 256;
    const uint32_t pBhi = sbase, pBlo = sbase + PB;

    const float bb0 = bbil[0], bb1 = bbil[1];
    const int crow = lane >> 2, cj = lane & 3;

    #pragma unroll 1
    for (int c = 0; c < 8; c++) {
        cp_wait0();
        __syncthreads();                           // buf[c&1] full, prior reads done
        if (c < 7) {
            issue_A_chunk(sbase + 65536 + ((c + 1) & 1) * 65536, b, ihalf * 512 + (c + 1) * 64, tid);
            cp_commit();
        }
        const uint32_t Abuf = sbase + 65536 + (c & 1) * 65536;

        float acc[2][2][4][4];
        #pragma unroll
        for (int k = 0; k < 2; k++)
            #pragma unroll
            for (int mi = 0; mi < 2; mi++)
                #pragma unroll
                for (int ni = 0; ni < 4; ni++)
                    #pragma unroll
                    for (int e = 0; e < 4; e++) acc[k][mi][ni][e] = 0.f;

        #pragma unroll 2
        for (int ks = 0; ks < 8; ks++) {
            const uint32_t kcol = (uint32_t)ks * 32;
            uint32_t bh[4][2], blf[4][2];
            #pragma unroll
            for (int ni = 0; ni < 4; ni++) {
                const uint32_t boff = bbase + ni * 2048 + ((kcol + bcoff) ^ bsw);
                ldsm2(bh[ni][0],  bh[ni][1],  pBhi + boff);
                ldsm2(blf[ni][0], blf[ni][1], pBlo + boff);
            }
            #pragma unroll
            for (int k = 0; k < 2; k++) {
                const uint32_t pAhi = Abuf + (2 * k + 0) * SUBP;
                const uint32_t pAlo = Abuf + (2 * k + 1) * SUBP;
                {
                    uint32_t ah[2][4];
                    #pragma unroll
                    for (int mi = 0; mi < 2; mi++)
                        ldsm4(ah[mi][0], ah[mi][1], ah[mi][2], ah[mi][3],
                              pAhi + abase + mi * 4096 + ((kcol + acoff) ^ asw));
                    #pragma unroll
                    for (int mi = 0; mi < 2; mi++)
                        #pragma unroll
                        for (int ni = 0; ni < 4; ni++) {
                            mma_bf16(acc[k][mi][ni], ah[mi], bh[ni]);
                            mma_bf16(acc[k][mi][ni], ah[mi], blf[ni]);
                        }
                }
                {
                    uint32_t al[2][4];
                    #pragma unroll
                    for (int mi = 0; mi < 2; mi++)
                        ldsm4(al[mi][0], al[mi][1], al[mi][2], al[mi][3],
                              pAlo + abase + mi * 4096 + ((kcol + acoff) ^ asw));
                    #pragma unroll
                    for (int mi = 0; mi < 2; mi++)
                        #pragma unroll
                        for (int ni = 0; ni < 4; ni++)
                            mma_bf16(acc[k][mi][ni], al[mi], bh[ni]);
                }
            }
        }

        // epilogue for this chunk
        const int ibase = ihalf * 512 + c * 64;
        #pragma unroll
        for (int mi = 0; mi < 2; mi++) {
            #pragma unroll
            for (int ni = 0; ni < 4; ni++) {
                const int j2 = wn * 16 + ni * 4 + cj;
                const int jj = j0 + j2 * 2;
                {
                    const int r = wm * 32 + mi * 16 + crow;
                    float4 v = make_float4(acc[0][mi][ni][0] + bb0, acc[1][mi][ni][0] + bb1,
                                           acc[0][mi][ni][1] + bb0, acc[1][mi][ni][1] + bb1);
                    *(float4*)(out + ((size_t)b * N_ + ibase + r) * N_ + jj) = v;
                }
                {
                    const int r = wm * 32 + mi * 16 + crow + 8;
                    float4 v = make_float4(acc[0][mi][ni][2] + bb0, acc[1][mi][ni][2] + bb1,
                                           acc[0][mi][ni][3] + bb0, acc[1][mi][ni][3] + bb1);
                    *(float4*)(out + ((size_t)b * N_ + ibase + r) * N_ + jj) = v;
                }
            }
        }
    }
}

// =====================================================================
extern "C" void kernel_launch(void* const* d_in, const int* in_sizes, int n_in,
                              void* d_out, int out_size)
{
    (void)in_sizes; (void)n_in; (void)out_size;
    const float* x  = (const float*)d_in[0];
    const float* Wl = (const float*)d_in[1];
    const float* bl = (const float*)d_in[2];
    const float* Wr = (const float*)d_in[3];
    const float* br = (const float*)d_in[4];
    const float* Wb = (const float*)d_in[5];
    const float* bb = (const float*)d_in[6];

    const int smemH = 4 * HP;        // 196,608 B
    const int smemT = 4 * PB;        // 131,072 B
    const int smemC = PAIR_SMEM;     // 196,608 B
    cudaFuncSetAttribute(hidden_kernel, cudaFuncAttributeMaxDynamicSharedMemorySize, smemH);
    cudaFuncSetAttribute(tform_kernel,  cudaFuncAttributeMaxDynamicSharedMemorySize, smemT);
    cudaFuncSetAttribute(pair_kernel,   cudaFuncAttributeMaxDynamicSharedMemorySize, smemC);

    prep_kernel  <<<320, 256>>>(Wl, Wr, Wb);
    hidden_kernel<<<dim3(8, B_, 2), 256, smemH>>>(x, bl, br);
    tform_kernel <<<dim3(8, B_, 2), 256, smemT>>>();
    pair_kernel  <<<dim3(8, B_, 2), 256, smemC>>>(bb, (float2*)d_out);
}

// round 15
// speedup vs baseline: 5.7412x; 1.0165x over previous
#include <cuda_runtime.h>
#include <cuda_bf16.h>
#include <cstdint>

#define B_   8
#define N_   1024
#define NIN_ 64
#define H_   128
#define F_   192

typedef unsigned long long u64;

// ---------------- scratch (device globals) ----------------
__device__ __align__(16) char g_Wsw_hi[2 * 49152];   // W sides, 384B-pitch swizzled
__device__ __align__(16) char g_Wsw_lo[2 * 49152];
__device__ __align__(16) char g_WbT_hi[2 * 32768];   // W_bil^T per k, 256B-pitch swizzled
__device__ __align__(16) char g_WbT_lo[2 * 32768];
__device__ __align__(16) __nv_bfloat16 g_hlb_hi[B_ * N_ * H_];
__device__ __align__(16) __nv_bfloat16 g_hlb_lo[B_ * N_ * H_];
__device__ __align__(16) __nv_bfloat16 g_hr_hi[B_ * N_ * H_];
__device__ __align__(16) __nv_bfloat16 g_hr_lo[B_ * N_ * H_];
__device__ __align__(16) __nv_bfloat16 g_t_hi[2 * B_ * N_ * H_];
__device__ __align__(16) __nv_bfloat16 g_t_lo[2 * B_ * N_ * H_];

__device__ __forceinline__ uint32_t smem_u32(const void* p) {
    uint32_t a;
    asm("{ .reg .u64 t; cvta.to.shared.u64 t, %1; cvt.u32.u64 %0, t; }" : "=r"(a) : "l"(p));
    return a;
}
// ---------------- tensor-core primitives (no 'a'-suffix PTX) ----------------
__device__ __forceinline__ void ldsm4(uint32_t& a0, uint32_t& a1, uint32_t& a2, uint32_t& a3, uint32_t addr) {
    asm volatile("ldmatrix.sync.aligned.m8n8.x4.shared.b16 {%0,%1,%2,%3}, [%4];"
        : "=r"(a0), "=r"(a1), "=r"(a2), "=r"(a3) : "r"(addr));
}
__device__ __forceinline__ void ldsm2(uint32_t& b0, uint32_t& b1, uint32_t addr) {
    asm volatile("ldmatrix.sync.aligned.m8n8.x2.shared.b16 {%0,%1}, [%2];"
        : "=r"(b0), "=r"(b1) : "r"(addr));
}
__device__ __forceinline__ void mma_bf16(float* c, const uint32_t* a, const uint32_t* b) {
    asm volatile("mma.sync.aligned.m16n8k16.row.col.f32.bf16.bf16.f32 "
        "{%0,%1,%2,%3}, {%4,%5,%6,%7}, {%8,%9}, {%0,%1,%2,%3};"
        : "+f"(c[0]), "+f"(c[1]), "+f"(c[2]), "+f"(c[3])
        : "r"(a[0]), "r"(a[1]), "r"(a[2]), "r"(a[3]), "r"(b[0]), "r"(b[1]));
}
__device__ __forceinline__ void split_bf16(float v, __nv_bfloat16& hi, __nv_bfloat16& lo) {
    hi = __float2bfloat16_rn(v);
    lo = __float2bfloat16_rn(v - __bfloat162float(hi));
}
// ---------------- cp.async ----------------
__device__ __forceinline__ void cp16(uint32_t dst, const void* src) {
    asm volatile("cp.async.cg.shared.global [%0], [%1], 16;" :: "r"(dst), "l"(src));
}
__device__ __forceinline__ void cp_commit() { asm volatile("cp.async.commit_group;" ::: "memory"); }
__device__ __forceinline__ void cp_wait0()  { asm volatile("cp.async.wait_group 0;" ::: "memory"); }

// =====================================================================
// prep: W -> bf16 hi/lo planes, pre-swizzled (unchanged)
// =====================================================================
__global__ __launch_bounds__(256)
void prep_kernel(const float* __restrict__ Wl, const float* __restrict__ Wr,
                 const float* __restrict__ Wbil)
{
    const int t = blockIdx.x * 256 + threadIdx.x;
    if (t < 2 * H_ * F_) {
        int side = t / (H_ * F_), r = t % (H_ * F_);
        int h = r / F_, f = r % F_;
        float v = (side ? Wr : Wl)[r];
        __nv_bfloat16 hi, lo; split_bf16(v, hi, lo);
        uint32_t byte = (uint32_t)h * 384u + (((uint32_t)f * 2u) ^ (((uint32_t)h & 7u) << 4));
        *(__nv_bfloat16*)(g_Wsw_hi + side * 49152 + byte) = hi;
        *(__nv_bfloat16*)(g_Wsw_lo + side * 49152 + byte) = lo;
    } else if (t < 2 * H_ * F_ + 2 * H_ * H_) {
        int r = t - 2 * H_ * F_;
        int k = r / (H_ * H_), rr = r % (H_ * H_);
        int g = rr / H_, h = rr % H_;
        float v = Wbil[k * H_ * H_ + h * H_ + g];
        __nv_bfloat16 hi, lo; split_bf16(v, hi, lo);
        uint32_t byte = (uint32_t)g * 256u + (((uint32_t)h * 2u) ^ (((uint32_t)g & 7u) << 4));
        *(__nv_bfloat16*)(g_WbT_hi + k * 32768 + byte) = hi;
        *(__nv_bfloat16*)(g_WbT_lo + k * 32768 + byte) = lo;
    }
}

// =====================================================================
// Kernel A (HMMA, unchanged)
// =====================================================================
#define HP 49152

__global__ __launch_bounds__(256, 1)
void hidden_kernel(const float* __restrict__ x,
                   const float* __restrict__ bl, const float* __restrict__ br)
{
    extern __shared__ char smc[];
    const int i0   = blockIdx.x * 128;
    const int b    = blockIdx.y;
    const int side = blockIdx.z;
    const int tid  = threadIdx.x;

    {
        const uint4* sh = (const uint4*)(g_Wsw_hi + side * HP);
        const uint4* sl = (const uint4*)(g_Wsw_lo + side * HP);
        uint4* dh = (uint4*)(smc + 2 * HP);
        uint4* dl = (uint4*)(smc + 3 * HP);
        #pragma unroll
        for (int it = 0; it < 12; it++) {
            dh[tid + it * 256] = sh[tid + it * 256];
            dl[tid + it * 256] = sl[tid + it * 256];
        }
    }
    const float* xb = x + (size_t)b * N_ * NIN_;
    #pragma unroll
    for (int seg = 0; seg < 3; seg++) {
        const int off = (seg == 0) ? 0 : (((seg == 1) == (side == 0)) ? -1 : 1);
        #pragma unroll 4
        for (int it = 0; it < 16; it++) {
            int idx = tid + it * 256;
            int m = idx >> 5, cp = idx & 31;
            int gi = i0 + m + off;
            float2 v = (gi >= 0 && gi < N_) ? *(const float2*)(xb + gi * NIN_ + cp * 2)
                                            : make_float2(0.f, 0.f);
            __nv_bfloat16 h0, l0, h1, l1;
            split_bf16(v.x, h0, l0); split_bf16(v.y, h1, l1);
            uint32_t byte = (uint32_t)m * 384u +
                (((uint32_t)(seg * 128 + cp * 4)) ^ (((uint32_t)m & 7u) << 4));
            *(__nv_bfloat162*)(smc + byte)      = __nv_bfloat162(h0, h1);
            *(__nv_bfloat162*)(smc + HP + byte) = __nv_bfloat162(l0, l1);
        }
    }
    __syncthreads();

    const int warp = tid >> 5, lane = tid & 31;
    const int wm = warp >> 2, wn = warp & 3;
    const int arowl = wm * 64 + ((lane >> 3) & 1) * 8 + (lane & 7);
    const uint32_t acoff = (lane >> 4) * 16;
    const uint32_t asw = (arowl & 7) << 4;
    const uint32_t abase = (uint32_t)arowl * 384;
    const int l16 = lane & 15;
    const int browl = wn * 32 + (l16 & 7);
    const uint32_t bcoff = ((l16 >> 3) & 1) * 16;
    const uint32_t bsw = (browl & 7) << 4;
    const uint32_t bbase = (uint32_t)browl * 384;

    const uint32_t sb = smem_u32(smc);
    const uint32_t pAhi = sb, pAlo = sb + HP, pBhi = sb + 2 * HP, pBlo = sb + 3 * HP;

    float acc[4][4][4];
    #pragma unroll
    for (int mi = 0; mi < 4; mi++)
        #pragma unroll
        for (int ni = 0; ni < 4; ni++)
            #pragma unroll
            for (int e = 0; e < 4; e++) acc[mi][ni][e] = 0.f;

    #pragma unroll 1
    for (int pass = 0; pass < 3; pass++) {
        const uint32_t pa = (pass == 2) ? pAlo : pAhi;
        const uint32_t pb = (pass == 1) ? pBlo : pBhi;
        #pragma unroll 4
        for (int ks = 0; ks < 12; ks++) {
            const uint32_t kcol = (uint32_t)ks * 32;
            uint32_t a[4][4], bf[4][2];
            #pragma unroll
            for (int mi = 0; mi < 4; mi++)
                ldsm4(a[mi][0], a[mi][1], a[mi][2], a[mi][3],
                      pa + abase + mi * 16 * 384 + ((kcol + acoff) ^ asw));
            #pragma unroll
            for (int ni = 0; ni < 4; ni++)
                ldsm2(bf[ni][0], bf[ni][1],
                      pb + bbase + ni * 8 * 384 + ((kcol + bcoff) ^ bsw));
            #pragma unroll
            for (int mi = 0; mi < 4; mi++)
                #pragma unroll
                for (int ni = 0; ni < 4; ni++)
                    mma_bf16(acc[mi][ni], a[mi], bf[ni]);
        }
    }

    const int crow = lane >> 2, cj = lane & 3;
    const float* bias = side ? br : bl;
    __nv_bfloat16* dhi = side ? g_hr_hi : g_hlb_hi;
    __nv_bfloat16* dlo = side ? g_hr_lo : g_hlb_lo;
    #pragma unroll
    for (int mi = 0; mi < 4; mi++) {
        #pragma unroll
        for (int ni = 0; ni < 4; ni++) {
            const int h0 = wn * 32 + ni * 8 + 2 * cj;
            const float2 bv = *(const float2*)(bias + h0);
            #pragma unroll
            for (int half = 0; half < 2; half++) {
                const int r = wm * 64 + mi * 16 + crow + half * 8;
                float v0 = fmaxf(acc[mi][ni][2 * half + 0] + bv.x, 0.f);
                float v1 = fmaxf(acc[mi][ni][2 * half + 1] + bv.y, 0.f);
                __nv_bfloat16 h0b, l0b, h1b, l1b;
                split_bf16(v0, h0b, l0b); split_bf16(v1, h1b, l1b);
                const size_t o = ((size_t)b * N_ + i0 + r) * H_ + h0;
                *(__nv_bfloat162*)(dhi + o) = __nv_bfloat162(h0b, h1b);
                *(__nv_bfloat162*)(dlo + o) = __nv_bfloat162(l0b, l1b);
            }
        }
    }
}

// =====================================================================
// Kernel B (HMMA, unchanged)
// =====================================================================
#define PB 32768

__device__ __forceinline__ void load_plane(char* dst, const __nv_bfloat16* src, int tid)
{
    const uint4* s = (const uint4*)src;
    #pragma unroll
    for (int it = 0; it < 8; it++) {
        int idx = tid + it * 256;
        int row = idx >> 4, c16 = idx & 15;
        uint32_t byte = row * 256 + ((c16 * 16) ^ ((row & 7) << 4));
        *(uint4*)(dst + byte) = s[idx];
    }
}

__global__ __launch_bounds__(256, 1)
void tform_kernel()
{
    extern __shared__ char smc[];
    const int i0 = blockIdx.x * 128;
    const int b  = blockIdx.y;
    const int k  = blockIdx.z;
    const int tid = threadIdx.x;

    const size_t arow = ((size_t)b * N_ + i0) * H_;
    load_plane(smc + 0 * PB, g_hlb_hi + arow, tid);
    load_plane(smc + 1 * PB, g_hlb_lo + arow, tid);
    {
        const uint4* sh = (const uint4*)(g_WbT_hi + k * PB);
        const uint4* sl = (const uint4*)(g_WbT_lo + k * PB);
        uint4* dh = (uint4*)(smc + 2 * PB);
        uint4* dl = (uint4*)(smc + 3 * PB);
        #pragma unroll
        for (int it = 0; it < 8; it++) {
            dh[tid + it * 256] = sh[tid + it * 256];
            dl[tid + it * 256] = sl[tid + it * 256];
        }
    }
    __syncthreads();

    const int warp = tid >> 5, lane = tid & 31;
    const int wm = warp >> 2, wn = warp & 3;
    const int arowl = wm * 64 + ((lane >> 3) & 1) * 8 + (lane & 7);
    const uint32_t acoff = (lane >> 4) * 16;
    const uint32_t asw = (arowl & 7) << 4;
    const uint32_t abase = (uint32_t)arowl * 256;
    const int l16 = lane & 15;
    const int browl = wn * 32 + (l16 & 7);
    const uint32_t bcoff = ((l16 >> 3) & 1) * 16;
    const uint32_t bsw = (browl & 7) << 4;
    const uint32_t bbase = (uint32_t)browl * 256;

    const uint32_t sb = smem_u32(smc);
    const uint32_t pAhi = sb, pAlo = sb + PB, pBhi = sb + 2 * PB, pBlo = sb + 3 * PB;

    float acc[4][4][4];
    #pragma unroll
    for (int mi = 0; mi < 4; mi++)
        #pragma unroll
        for (int ni = 0; ni < 4; ni++)
            #pragma unroll
            for (int e = 0; e < 4; e++) acc[mi][ni][e] = 0.f;

    #pragma unroll 1
    for (int pass = 0; pass < 3; pass++) {
        const uint32_t pa = (pass == 2) ? pAlo : pAhi;
        const uint32_t pb = (pass == 1) ? pBlo : pBhi;
        #pragma unroll 4
        for (int ks = 0; ks < 8; ks++) {
            const uint32_t kcol = (uint32_t)ks * 32;
            uint32_t a[4][4], bf[4][2];
            #pragma unroll
            for (int mi = 0; mi < 4; mi++)
                ldsm4(a[mi][0], a[mi][1], a[mi][2], a[mi][3],
                      pa + abase + mi * 4096 + ((kcol + acoff) ^ asw));
            #pragma unroll
            for (int ni = 0; ni < 4; ni++)
                ldsm2(bf[ni][0], bf[ni][1],
                      pb + bbase + ni * 2048 + ((kcol + bcoff) ^ bsw));
            #pragma unroll
            for (int mi = 0; mi < 4; mi++)
                #pragma unroll
                for (int ni = 0; ni < 4; ni++)
                    mma_bf16(acc[mi][ni], a[mi], bf[ni]);
        }
    }

    const int crow = lane >> 2, cj = lane & 3;
    __nv_bfloat16* dhi = g_t_hi + (size_t)k * B_ * N_ * H_;
    __nv_bfloat16* dlo = g_t_lo + (size_t)k * B_ * N_ * H_;
    #pragma unroll
    for (int mi = 0; mi < 4; mi++) {
        #pragma unroll
        for (int ni = 0; ni < 4; ni++) {
            const int g0 = wn * 32 + ni * 8 + 2 * cj;
            #pragma unroll
            for (int half = 0; half < 2; half++) {
                const int r = wm * 64 + mi * 16 + crow + half * 8;
                float v0 = acc[mi][ni][2 * half + 0];
                float v1 = acc[mi][ni][2 * half + 1];
                __nv_bfloat16 h0b, l0b, h1b, l1b;
                split_bf16(v0, h0b, l0b); split_bf16(v1, h1b, l1b);
                const size_t o = ((size_t)b * N_ + i0 + r) * H_ + g0;
                *(__nv_bfloat162*)(dhi + o) = __nv_bfloat162(h0b, h1b);
                *(__nv_bfloat162*)(dlo + o) = __nv_bfloat162(l0b, l1b);
            }
        }
    }
}

// =====================================================================
// Kernel C v4: persistent pipelined pair GEMM, 512 threads (16 warps,
//   4/SMSP) in a 4(m) x 4(n) grid; warp tile 16m x 32n per 64-row chunk.
//   Same smem layout / swizzle / cp.async double-buffering as v3.
// =====================================================================
#define PAIR_SMEM 196608
#define SUBP 16384            // 64 rows x 256B sub-plane

__device__ __forceinline__ void issue_A_chunk(uint32_t dstbase, int b, int i0c, int tid)
{
    const size_t bnh = (size_t)B_ * N_ * H_;
    const size_t rowbase = ((size_t)b * N_ + i0c) * H_;
    #pragma unroll
    for (int it = 0; it < 8; it++) {
        int idx = tid + it * 512;                 // 4096 x 16B
        int sub = idx >> 10;                      // 0..3 : k0hi,k0lo,k1hi,k1lo
        int k = sub >> 1, p = sub & 1;
        int r = (idx >> 4) & 63, c16 = idx & 15;
        const __nv_bfloat16* src = (p ? g_t_lo : g_t_hi) + k * bnh + rowbase + (size_t)r * H_ + c16 * 8;
        uint32_t dst = dstbase + sub * SUBP + r * 256 + ((c16 * 16) ^ ((r & 7) << 4));
        cp16(dst, src);
    }
}

__global__ __launch_bounds__(512, 1)
void pair_kernel(const float* __restrict__ bbil, float2* __restrict__ out)
{
    extern __shared__ char smc[];
    const uint32_t sbase = smem_u32(smc);
    const int j0    = blockIdx.x * 128;
    const int b     = blockIdx.y;
    const int ihalf = blockIdx.z;
    const int tid = threadIdx.x;
    const int warp = tid >> 5, lane = tid & 31;
    const int wm = warp >> 2, wn = warp & 3;     // 4(m) x 4(n)

    // --- B planes (hr hi/lo) via cp.async, swizzled ---
    {
        #pragma unroll
        for (int it = 0; it < 8; it++) {
            int idx = tid + it * 512;             // 4096 x 16B
            int p = idx >> 11;                    // 0 hi, 1 lo
            int r = (idx >> 4) & 127, c16 = idx & 15;
            const __nv_bfloat16* src = (p ? g_hr_lo : g_hr_hi) + ((size_t)b * N_ + j0 + r) * H_ + c16 * 8;
            uint32_t dst = sbase + p * PB + r * 256 + ((c16 * 16) ^ ((r & 7) << 4));
            cp16(dst, src);
        }
    }
    issue_A_chunk(sbase + 65536, b, ihalf * 512, tid);
    cp_commit();

    // lane geometry: A row = wm*16 + ldmatrix row; B identical to r13 layout
    const int arowl = wm * 16 + ((lane >> 3) & 1) * 8 + (lane & 7);
    const uint32_t acoff = (lane >> 4) * 16;
    const uint32_t asw = (arowl & 7) << 4;
    const uint32_t abase = (uint32_t)arowl * 256;
    const int l16 = lane & 15;
    const int browl = wn * 32 + (l16 & 7);
    const uint32_t bcoff = ((l16 >> 3) & 1) * 16;
    const uint32_t bsw = (browl & 7) << 4;
    const uint32_t bbase = (uint32_t)browl * 256;
    const uint32_t pBhi = sbase, pBlo = sbase + PB;

    const float bb0 = bbil[0], bb1 = bbil[1];
    const int crow = lane >> 2, cj = lane & 3;

    #pragma unroll 1
    for (int c = 0; c < 8; c++) {
        cp_wait0();
        __syncthreads();                           // buf[c&1] full, prior reads done
        if (c < 7) {
            issue_A_chunk(sbase + 65536 + ((c + 1) & 1) * 65536, b, ihalf * 512 + (c + 1) * 64, tid);
            cp_commit();
        }
        const uint32_t Abuf = sbase + 65536 + (c & 1) * 65536;

        float acc[2][4][4];                        // [k][ni][elem]
        #pragma unroll
        for (int k = 0; k < 2; k++)
            #pragma unroll
            for (int ni = 0; ni < 4; ni++)
                #pragma unroll
                for (int e = 0; e < 4; e++) acc[k][ni][e] = 0.f;

        #pragma unroll 2
        for (int ks = 0; ks < 8; ks++) {
            const uint32_t kcol = (uint32_t)ks * 32;
            uint32_t bh[4][2], blf[4][2];
            #pragma unroll
            for (int ni = 0; ni < 4; ni++) {
                const uint32_t boff = bbase + ni * 2048 + ((kcol + bcoff) ^ bsw);
                ldsm2(bh[ni][0],  bh[ni][1],  pBhi + boff);
                ldsm2(blf[ni][0], blf[ni][1], pBlo + boff);
            }
            #pragma unroll
            for (int k = 0; k < 2; k++) {
                const uint32_t pAhi = Abuf + (2 * k + 0) * SUBP;
                const uint32_t pAlo = Abuf + (2 * k + 1) * SUBP;
                {
                    uint32_t ah[4];
                    ldsm4(ah[0], ah[1], ah[2], ah[3],
                          pAhi + abase + ((kcol + acoff) ^ asw));
                    #pragma unroll
                    for (int ni = 0; ni < 4; ni++) {
                        mma_bf16(acc[k][ni], ah, bh[ni]);
                        mma_bf16(acc[k][ni], ah, blf[ni]);
                    }
                }
                {
                    uint32_t al[4];
                    ldsm4(al[0], al[1], al[2], al[3],
                          pAlo + abase + ((kcol + acoff) ^ asw));
                    #pragma unroll
                    for (int ni = 0; ni < 4; ni++)
                        mma_bf16(acc[k][ni], al, bh[ni]);
                }
            }
        }

        // epilogue for this chunk
        const int ibase = ihalf * 512 + c * 64;
        #pragma unroll
        for (int ni = 0; ni < 4; ni++) {
            const int j2 = wn * 16 + ni * 4 + cj;
            const int jj = j0 + j2 * 2;
            {
                const int r = wm * 16 + crow;
                float4 v = make_float4(acc[0][ni][0] + bb0, acc[1][ni][0] + bb1,
                                       acc[0][ni][1] + bb0, acc[1][ni][1] + bb1);
                *(float4*)(out + ((size_t)b * N_ + ibase + r) * N_ + jj) = v;
            }
            {
                const int r = wm * 16 + crow + 8;
                float4 v = make_float4(acc[0][ni][2] + bb0, acc[1][ni][2] + bb1,
                                       acc[0][ni][3] + bb0, acc[1][ni][3] + bb1);
                *(float4*)(out + ((size_t)b * N_ + ibase + r) * N_ + jj) = v;
            }
        }
    }
}

// =====================================================================
extern "C" void kernel_launch(void* const* d_in, const int* in_sizes, int n_in,
                              void* d_out, int out_size)
{
    (void)in_sizes; (void)n_in; (void)out_size;
    const float* x  = (const float*)d_in[0];
    const float* Wl = (const float*)d_in[1];
    const float* bl = (const float*)d_in[2];
    const float* Wr = (const float*)d_in[3];
    const float* br = (const float*)d_in[4];
    const float* Wb = (const float*)d_in[5];
    const float* bb = (const float*)d_in[6];

    const int smemH = 4 * HP;        // 196,608 B
    const int smemT = 4 * PB;        // 131,072 B
    const int smemC = PAIR_SMEM;     // 196,608 B
    cudaFuncSetAttribute(hidden_kernel, cudaFuncAttributeMaxDynamicSharedMemorySize, smemH);
    cudaFuncSetAttribute(tform_kernel,  cudaFuncAttributeMaxDynamicSharedMemorySize, smemT);
    cudaFuncSetAttribute(pair_kernel,   cudaFuncAttributeMaxDynamicSharedMemorySize, smemC);

    prep_kernel  <<<320, 256>>>(Wl, Wr, Wb);
    hidden_kernel<<<dim3(8, B_, 2), 256, smemH>>>(x, bl, br);
    tform_kernel <<<dim3(8, B_, 2), 256, smemT>>>();
    pair_kernel  <<<dim3(8, B_, 2), 512, smemC>>>(bb, (float2*)d_out);
}